// round 2
// baseline (speedup 1.0000x reference)
#include <cuda_runtime.h>

#define DD   48
#define HW   2304            // 48*48
#define DHW  110592          // 48^3
#define CIN  128
#define COUT 128
#define NK   512
#define KK   3456            // 128*27
#define LOG2E 1.4426950408889634f

// ---------------- scratch (device globals; no allocation allowed) ----------------
__device__ float d_y[COUT * DHW];     // conv+relu output, 56.6 MB
__device__ float d_wt[COUT * KK];     // transposed weights [cin][tap][cout]
__device__ float d_mean[COUT];
__device__ float d_rstd[COUT];
__device__ float d_fk2[NK * 128];     // 2*log2e * normalized keypoint features, [n][c]
__device__ float d_nn[NK];            // log2e * ||fk_n||^2

__device__ __forceinline__ float exp2a(float x) {
    float r;
    asm("ex2.approx.ftz.f32 %0, %1;" : "=f"(r) : "f"(x));
    return r;
}

// ---------------- kernel 0: transpose W0 (co,cin,tap) -> (cin,tap,co) ----------------
__global__ void transpose_w_kernel(const float* __restrict__ W0) {
    int i = blockIdx.x * 256 + threadIdx.x;          // 442368 = 1728*256 exactly
    int co  = i & 127;
    int tap = (i >> 7) % 27;
    int cin = i / KK;
    d_wt[i] = W0[co * KK + cin * 27 + tap];
}

// ---------------- kernel 1: conv3d(3x3x3, pad1) + bias + relu ----------------
// block: 256 thr, computes a 4x4x4 spatial tile x all 128 couts.
// thread mapping: gidx = tid&15 -> (sz,sy); sx = 0..3 per-thread; co_base = (tid>>4)*8
__global__ void __launch_bounds__(256) conv_relu_kernel(const float* __restrict__ feats,
                                                        const float* __restrict__ b0) {
    __shared__ __align__(16) float patch[216];       // 6x6x6
    __shared__ __align__(16) float wsm[KK];          // [tap][co] for current cin

    const int tid = threadIdx.x;
    const int blk = blockIdx.x;
    const int tz = blk / 144, ty = (blk / 12) % 12, tx = blk % 12;

    const int gidx = tid & 15;
    const int sz = gidx >> 2, sy = gidx & 3;
    const int co_base = (tid >> 4) * 8;

    float acc[4][8];
#pragma unroll
    for (int i = 0; i < 4; i++)
#pragma unroll
        for (int j = 0; j < 8; j++) acc[i][j] = 0.f;

    // precompute patch-load coords for this thread (tid<216 loads one element)
    int gz = 0, gy = 0, gx = 0;
    bool inb = false;
    if (tid < 216) {
        int pz = tid / 36, py = (tid / 6) % 6, px = tid % 6;
        gz = tz * 4 + pz - 1;
        gy = ty * 4 + py - 1;
        gx = tx * 4 + px - 1;
        inb = (gz >= 0 && gz < DD && gy >= 0 && gy < DD && gx >= 0 && gx < DD);
    }

    for (int cin = 0; cin < CIN; ++cin) {
        if (tid < 216) {
            float v = 0.f;
            if (inb) {
                if (cin < 125)      v = feats[cin * DHW + gz * HW + gy * 48 + gx];
                else if (cin == 125) v = (2.0f / 47.0f) * (float)gx - 1.0f;
                else if (cin == 126) v = (2.0f / 47.0f) * (float)gy - 1.0f;
                else                 v = (2.0f / 47.0f) * (float)gz - 1.0f;
            }
            patch[tid] = v;
        }
        const float* wsrc = &d_wt[cin * KK];
        for (int i = tid; i < KK; i += 256) wsm[i] = wsrc[i];
        __syncthreads();

#pragma unroll
        for (int kz = 0; kz < 3; ++kz)
#pragma unroll
        for (int ky = 0; ky < 3; ++ky)
#pragma unroll
        for (int kx = 0; kx < 3; ++kx) {
            const int base = (sz + kz) * 36 + (sy + ky) * 6 + kx;
            float in[4];
            in[0] = patch[base + 0];
            in[1] = patch[base + 1];
            in[2] = patch[base + 2];
            in[3] = patch[base + 3];
            const int tap = (kz * 3 + ky) * 3 + kx;
            float4 wa = *reinterpret_cast<const float4*>(&wsm[tap * 128 + co_base]);
            float4 wb = *reinterpret_cast<const float4*>(&wsm[tap * 128 + co_base + 4]);
            float w[8] = {wa.x, wa.y, wa.z, wa.w, wb.x, wb.y, wb.z, wb.w};
#pragma unroll
            for (int i = 0; i < 4; i++)
#pragma unroll
                for (int j = 0; j < 8; j++)
                    acc[i][j] = fmaf(in[i], w[j], acc[i][j]);
        }
        __syncthreads();
    }

    // write bias + relu
    const int z = tz * 4 + sz, y = ty * 4 + sy, xb = tx * 4;
#pragma unroll
    for (int j = 0; j < 8; j++) {
        const int co = co_base + j;
        const float b = b0[co];
        float* dst = &d_y[co * DHW + z * HW + y * 48 + xb];
#pragma unroll
        for (int i = 0; i < 4; i++) {
            dst[i] = fmaxf(acc[i][j] + b, 0.f);
        }
    }
}

// ---------------- kernel 2: per-channel mean / rstd (InstanceNorm stats) ----------------
__global__ void __launch_bounds__(256) stats_kernel() {
    const int c = blockIdx.x;
    const int tid = threadIdx.x;
    const float* src = &d_y[c * DHW];
    float s = 0.f, s2 = 0.f;
    for (int i = tid; i < DHW; i += 256) {
        float v = src[i];
        s += v;
        s2 += v * v;
    }
    __shared__ float rs[256], rs2[256];
    rs[tid] = s; rs2[tid] = s2;
    __syncthreads();
    for (int o = 128; o > 0; o >>= 1) {
        if (tid < o) { rs[tid] += rs[tid + o]; rs2[tid] += rs2[tid + o]; }
        __syncthreads();
    }
    if (tid == 0) {
        float mean = rs[0] * (1.0f / (float)DHW);
        float var  = rs2[0] * (1.0f / (float)DHW) - mean * mean;
        d_mean[c] = mean;
        d_rstd[c] = rsqrtf(var + 1e-5f);
    }
}

// ---------------- kernel 3: trilinear sample at keypoints, normalize, scale ----------------
__global__ void __launch_bounds__(128) sample_kernel(const float* __restrict__ kpts) {
    const int n = blockIdx.x;
    const int c = threadIdx.x;
    __shared__ float pt[3];
    if (c < 3) pt[c] = kpts[n * 3 + c];
    __syncthreads();

    const float ix = (pt[0] + 1.0f) * 0.5f * 47.0f;
    const float iy = (pt[1] + 1.0f) * 0.5f * 47.0f;
    const float iz = (pt[2] + 1.0f) * 0.5f * 47.0f;
    const float x0f = floorf(ix), y0f = floorf(iy), z0f = floorf(iz);
    const float wx = ix - x0f, wy = iy - y0f, wz = iz - z0f;
    int x0 = min(max((int)x0f, 0), 47);
    int y0 = min(max((int)y0f, 0), 47);
    int z0 = min(max((int)z0f, 0), 47);
    int x1 = min(x0 + 1, 47), y1 = min(y0 + 1, 47), z1 = min(z0 + 1, 47);

    const float* vol = &d_y[c * DHW];
    float c000 = vol[z0 * HW + y0 * 48 + x0];
    float c001 = vol[z0 * HW + y0 * 48 + x1];
    float c010 = vol[z0 * HW + y1 * 48 + x0];
    float c011 = vol[z0 * HW + y1 * 48 + x1];
    float c100 = vol[z1 * HW + y0 * 48 + x0];
    float c101 = vol[z1 * HW + y0 * 48 + x1];
    float c110 = vol[z1 * HW + y1 * 48 + x0];
    float c111 = vol[z1 * HW + y1 * 48 + x1];

    float v = c000 * ((1 - wz) * (1 - wy) * (1 - wx))
            + c001 * ((1 - wz) * (1 - wy) * wx)
            + c010 * ((1 - wz) * wy * (1 - wx))
            + c011 * ((1 - wz) * wy * wx)
            + c100 * (wz * (1 - wy) * (1 - wx))
            + c101 * (wz * (1 - wy) * wx)
            + c110 * (wz * wy * (1 - wx))
            + c111 * (wz * wy * wx);

    // normalization is per-channel affine, so it commutes with trilinear interp
    float f = (v - d_mean[c]) * d_rstd[c];
    d_fk2[n * 128 + c] = 2.0f * LOG2E * f;

    __shared__ float red[128];
    red[c] = f * f;
    __syncthreads();
    for (int o = 64; o > 0; o >>= 1) {
        if (c < o) red[c] += red[c + o];
        __syncthreads();
    }
    if (c == 0) d_nn[n] = LOG2E * red[0];
}

// ---------------- kernel 4: distances + softmax + weighted displacement ----------------
// weight_n(g) proportional to exp(2*dot(fg_g,fk_n) - ||fk_n||^2)  (||fg_g||^2 cancels)
// computed in log2 domain with online max-rescale.
// block: 256 thr = 32 voxels (lane=g) x 8 keypoint groups (q). 16 chunks of 32 kpts.
__global__ void __launch_bounds__(256) softmax_disp_kernel(const float* __restrict__ disp,
                                                           float* __restrict__ out) {
    __shared__ __align__(16) float fgs[128 * 32];   // [c][g]
    __shared__ __align__(16) float fks[32 * 128];   // [n_local][c]  (reused as reduction buf)
    __shared__ float nns[32];
    __shared__ float dsm[NK * 3];

    const int tid = threadIdx.x;
    const int g0 = blockIdx.x * 32;
    const int g = tid & 31;
    const int q = tid >> 5;

    for (int i = tid; i < 4096; i += 256) {
        int c = i >> 5, gg = i & 31;
        fgs[i] = (d_y[c * DHW + g0 + gg] - d_mean[c]) * d_rstd[c];
    }
    for (int i = tid; i < NK * 3; i += 256) dsm[i] = disp[i];

    float m = -1e30f, S = 0.f, Wx = 0.f, Wy = 0.f, Wz = 0.f;

    for (int ch = 0; ch < 16; ++ch) {
        __syncthreads();
        const float* fsrc = &d_fk2[ch * 4096];
        for (int i = tid; i < 4096; i += 256) fks[i] = fsrc[i];
        if (tid < 32) nns[tid] = d_nn[ch * 32 + tid];
        __syncthreads();

        const int nl0 = q * 4;
        float a0 = -nns[nl0 + 0];
        float a1 = -nns[nl0 + 1];
        float a2 = -nns[nl0 + 2];
        float a3 = -nns[nl0 + 3];

        const float* k0p = &fks[(nl0 + 0) * 128];
        const float* k1p = &fks[(nl0 + 1) * 128];
        const float* k2p = &fks[(nl0 + 2) * 128];
        const float* k3p = &fks[(nl0 + 3) * 128];

#pragma unroll 8
        for (int c = 0; c < 128; c += 4) {
            float f0 = fgs[(c + 0) * 32 + g];
            float f1 = fgs[(c + 1) * 32 + g];
            float f2 = fgs[(c + 2) * 32 + g];
            float f3 = fgs[(c + 3) * 32 + g];
            float4 k0 = *reinterpret_cast<const float4*>(k0p + c);
            float4 k1 = *reinterpret_cast<const float4*>(k1p + c);
            float4 k2 = *reinterpret_cast<const float4*>(k2p + c);
            float4 k3 = *reinterpret_cast<const float4*>(k3p + c);
            a0 = fmaf(f0, k0.x, a0); a0 = fmaf(f1, k0.y, a0); a0 = fmaf(f2, k0.z, a0); a0 = fmaf(f3, k0.w, a0);
            a1 = fmaf(f0, k1.x, a1); a1 = fmaf(f1, k1.y, a1); a1 = fmaf(f2, k1.z, a1); a1 = fmaf(f3, k1.w, a1);
            a2 = fmaf(f0, k2.x, a2); a2 = fmaf(f1, k2.y, a2); a2 = fmaf(f2, k2.z, a2); a2 = fmaf(f3, k2.w, a2);
            a3 = fmaf(f0, k3.x, a3); a3 = fmaf(f1, k3.y, a3); a3 = fmaf(f2, k3.z, a3); a3 = fmaf(f3, k3.w, a3);
        }

        float m8 = fmaxf(fmaxf(a0, a1), fmaxf(a2, a3));
        if (m8 > m) {
            float cs = exp2a(m - m8);
            S *= cs; Wx *= cs; Wy *= cs; Wz *= cs;
            m = m8;
        }
        const int nb = (ch * 32 + nl0) * 3;
        float e0 = exp2a(a0 - m);
        float e1 = exp2a(a1 - m);
        float e2 = exp2a(a2 - m);
        float e3 = exp2a(a3 - m);
        S += e0 + e1 + e2 + e3;
        Wx = fmaf(e0, dsm[nb + 0], fmaf(e1, dsm[nb + 3], fmaf(e2, dsm[nb + 6], fmaf(e3, dsm[nb + 9],  Wx))));
        Wy = fmaf(e0, dsm[nb + 1], fmaf(e1, dsm[nb + 4], fmaf(e2, dsm[nb + 7], fmaf(e3, dsm[nb + 10], Wy))));
        Wz = fmaf(e0, dsm[nb + 2], fmaf(e1, dsm[nb + 5], fmaf(e2, dsm[nb + 8], fmaf(e3, dsm[nb + 11], Wz))));
    }

    // combine across the 8 q-groups per voxel (reuse fks as reduction buffer)
    __syncthreads();
    float* red = fks;
    red[0 * 256 + tid] = m;
    red[1 * 256 + tid] = S;
    red[2 * 256 + tid] = Wx;
    red[3 * 256 + tid] = Wy;
    red[4 * 256 + tid] = Wz;
    __syncthreads();
    if (tid < 32) {
        float mm = -1e30f;
#pragma unroll
        for (int qq = 0; qq < 8; qq++) mm = fmaxf(mm, red[qq * 32 + tid]);
        float Ss = 0.f, Sx = 0.f, Sy = 0.f, Sz = 0.f;
#pragma unroll
        for (int qq = 0; qq < 8; qq++) {
            float cs = exp2a(red[qq * 32 + tid] - mm);
            Ss = fmaf(red[256 + qq * 32 + tid], cs, Ss);
            Sx = fmaf(red[512 + qq * 32 + tid], cs, Sx);
            Sy = fmaf(red[768 + qq * 32 + tid], cs, Sy);
            Sz = fmaf(red[1024 + qq * 32 + tid], cs, Sz);
        }
        float inv = 1.0f / Ss;
        out[0 * DHW + g0 + tid] = Sx * inv;
        out[1 * DHW + g0 + tid] = Sy * inv;
        out[2 * DHW + g0 + tid] = Sz * inv;
    }
}

// ---------------- launch ----------------
extern "C" void kernel_launch(void* const* d_in, const int* in_sizes, int n_in,
                              void* d_out, int out_size) {
    const float* kpts  = (const float*)d_in[0];  // (1,512,3)
    const float* disp  = (const float*)d_in[1];  // (1,512,3)
    const float* feats = (const float*)d_in[2];  // (1,125,48,48,48)
    const float* W0    = (const float*)d_in[3];  // (128,128,3,3,3)
    const float* b0    = (const float*)d_in[4];  // (128,)
    float* out = (float*)d_out;                  // (1,3,48,48,48)

    transpose_w_kernel<<<1728, 256>>>(W0);
    conv_relu_kernel<<<1728, 256>>>(feats, b0);
    stats_kernel<<<128, 256>>>();
    sample_kernel<<<NK, 128>>>(kpts);
    softmax_disp_kernel<<<DHW / 32, 256>>>(disp, out);
}

// round 4
// speedup vs baseline: 1.6631x; 1.6631x over previous
#include <cuda_runtime.h>
#include <cuda_bf16.h>
#include <cstdint>

#define DD   48
#define HW   2304
#define DHW  110592
#define NK   512
#define LOG2E 1.4426950408889634f
#define NSTEPS 162

// ---------------- device scratch ----------------
__device__ __nv_bfloat16 d_xv[160002 * 256];          // padded split-bf16 input (+1-pos guard)
__device__ __nv_bfloat16 d_wb[27 * 128 * 384];        // weights [tap][co][bhi|bhi|blo]
__device__ float d_y[128 * DHW];
__device__ float d_mean[128];
__device__ float d_rstd[128];
__device__ float d_fk2[NK * 128];
__device__ float d_nn[NK];

__device__ __forceinline__ float exp2a(float x) {
    float r; asm("ex2.approx.ftz.f32 %0, %1;" : "=f"(r) : "f"(x)); return r;
}
__device__ __forceinline__ uint32_t smem_u32(const void* p) {
    uint32_t a;
    asm("{ .reg .u64 t; cvta.to.shared.u64 t, %1; cvt.u32.u64 %0, t; }" : "=r"(a) : "l"(p));
    return a;
}
__device__ __forceinline__ void cp16(uint32_t dst, const void* src) {
    asm volatile("cp.async.cg.shared.global [%0], [%1], 16;" :: "r"(dst), "l"(src));
}
__device__ __forceinline__ void cp_commit() { asm volatile("cp.async.commit_group;"); }
__device__ __forceinline__ void ldsm4(uint32_t addr, uint32_t& r0, uint32_t& r1, uint32_t& r2, uint32_t& r3) {
    asm volatile("ldmatrix.sync.aligned.m8n8.x4.shared.b16 {%0,%1,%2,%3}, [%4];"
                 : "=r"(r0), "=r"(r1), "=r"(r2), "=r"(r3) : "r"(addr));
}
__device__ __forceinline__ void mma16816(float* c, const uint32_t* a, uint32_t b0, uint32_t b1) {
    asm volatile("mma.sync.aligned.m16n8k16.row.col.f32.bf16.bf16.f32 "
                 "{%0,%1,%2,%3}, {%4,%5,%6,%7}, {%8,%9}, {%0,%1,%2,%3};"
                 : "+f"(c[0]), "+f"(c[1]), "+f"(c[2]), "+f"(c[3])
                 : "r"(a[0]), "r"(a[1]), "r"(a[2]), "r"(a[3]), "r"(b0), "r"(b1));
}

// ---------------- pack input: padded [z50][y50][x64][hi128|lo128], +1 pos guard ----------------
__global__ void __launch_bounds__(256) convA_kernel(const float* __restrict__ feats) {
    __shared__ __nv_bfloat16 tb[64][264];
    const int r = blockIdx.x;                 // 0..2499 padded (z,y) rows
    const int zs = r / 50, ys = r % 50;
    const int zi = zs - 1, yi = ys - 1;
    const int tid = threadIdx.x;
    const int x = tid & 63, cq = tid >> 6;
    const int xi = x - 1;
    const bool rowok = (zi >= 0 && zi < 48 && yi >= 0 && yi < 48);
    const bool xok = rowok && (xi >= 0 && xi < 48);
#pragma unroll 4
    for (int i = 0; i < 32; ++i) {
        int c = cq * 32 + i;
        float v = 0.f;
        if (xok) {
            if (c < 125)       v = feats[c * DHW + zi * HW + yi * 48 + xi];
            else if (c == 125) v = (2.0f / 47.0f) * (float)xi - 1.0f;
            else if (c == 126) v = (2.0f / 47.0f) * (float)yi - 1.0f;
            else               v = (2.0f / 47.0f) * (float)zi - 1.0f;
        }
        __nv_bfloat16 hi = __float2bfloat16(v);
        tb[x][c] = hi;
        tb[x][128 + c] = __float2bfloat16(v - __bfloat162float(hi));
    }
    __syncthreads();
#pragma unroll
    for (int i = 0; i < 8; ++i) {
        int idx = i * 256 + tid;
        int xr = idx >> 5, k8 = idx & 31;
        float4 val = *(const float4*)&tb[xr][k8 * 8];
        *(float4*)(d_xv + (size_t)(r * 64 + xr + 1) * 256 + k8 * 8) = val;
    }
}

// ---------------- pack weights: [tap][co][k384] = [bhi(cin0-127), bhi, blo] ----------------
__global__ void __launch_bounds__(256) convW_kernel(const float* __restrict__ W0) {
    int idx = blockIdx.x * 256 + threadIdx.x;   // 5184 blocks = 27*128*384
    int kk = idx % 384;
    int co = (idx / 384) & 127;
    int tap = idx / (384 * 128);
    int cin = kk & 127;
    float v = W0[co * 3456 + cin * 27 + tap];
    __nv_bfloat16 hi = __float2bfloat16(v);
    d_wb[idx] = (kk < 256) ? hi : __float2bfloat16(v - __bfloat162float(hi));
}

// ---------------- conv3d via mma.sync bf16, 3-stage cp.async pipeline ----------------
// CTA: M=256 (4y x 64x), N=128 couts. 512 thr = 16 warps (4m x 4n), warp tile 64x32.
#define STG_SZ 49152               // A 32KB + B 16KB per stage
#define CONV_SMEM (3 * STG_SZ)

__global__ void __launch_bounds__(512, 1) conv_mma_kernel(const float* __restrict__ b0g) {
    extern __shared__ char smem[];
    const uint32_t sb = smem_u32(smem);
    const int tid = threadIdx.x;
    const int zc = blockIdx.x;        // 0..47
    const int y0 = blockIdx.y * 4;    // 0..44

    const int xx = tid >> 3;          // 0..63
    const int u  = tid & 7;           // 16B unit
    const uint32_t dstA0 = sb + xx * 128 + ((u ^ (xx & 7)) << 4);
    const uint32_t dstB0 = sb + 32768 + xx * 128 + ((u ^ (xx & 7)) << 4);
    static const int koA_t[6] = {0, 64, 128, 192, 0, 64};

    auto load_stage = [&](int buf, int tap, int s) {
        const int dz = tap / 9, dy = (tap / 9 * 9 == tap ? 0 : 0), dummy = 0;
        (void)dummy;
        const int dyv = (tap % 9) / 3, dx = tap % 3;
        const int koA = koA_t[s];
        // A: 4 rows (yy = 0..3)
        const size_t e0 = ((size_t)((zc + dz) * 50 + y0 + dyv) * 64 + xx + dx) * 256 + koA + u * 8;
        const __nv_bfloat16* asrc = d_xv + e0;
        uint32_t ad = dstA0 + buf * STG_SZ;
#pragma unroll
        for (int i = 0; i < 4; ++i)
            cp16(ad + i * 8192, asrc + (size_t)i * 16384);
        // B: 2 rows (co = xx, xx+64)
        const __nv_bfloat16* bsrc = d_wb + (size_t)tap * 49152 + (size_t)xx * 384 + s * 64 + u * 8;
        uint32_t bd = dstB0 + buf * STG_SZ;
#pragma unroll
        for (int i = 0; i < 2; ++i)
            cp16(bd + i * 8192, bsrc + (size_t)i * 64 * 384);
        cp_commit();
    };

    load_stage(0, 0, 0);
    load_stage(1, 0, 1);

    const int wid = tid >> 5, lane = tid & 31;
    const int wm = wid >> 2, wn = wid & 3;
    const int rA = wm * 64 + (lane & 15);
    const int uA = lane >> 4;
    const int rB = wn * 32 + ((lane >> 4) << 3) + (lane & 7);
    const int uB = (lane >> 3) & 1;

    float acc[4][4][4];
#pragma unroll
    for (int i = 0; i < 4; ++i)
#pragma unroll
        for (int j = 0; j < 4; ++j)
#pragma unroll
            for (int k = 0; k < 4; ++k) acc[i][j][k] = 0.f;

    for (int step = 0; step < NSTEPS; ++step) {
        if (step < NSTEPS - 1) asm volatile("cp.async.wait_group 1;");
        else                   asm volatile("cp.async.wait_group 0;");
        __syncthreads();
        const int next = step + 2;
        if (next < NSTEPS) load_stage(next % 3, next / 6, next % 6);

        const uint32_t As = sb + (step % 3) * STG_SZ;
        const uint32_t Bs = As + 32768;
#pragma unroll
        for (int k16 = 0; k16 < 4; ++k16) {
            uint32_t a[4][4], b4[2][4];
#pragma unroll
            for (int mt = 0; mt < 4; ++mt) {
                const int row = rA + mt * 16;
                ldsm4(As + row * 128 + (((k16 * 2 + uA) ^ (row & 7)) << 4),
                      a[mt][0], a[mt][1], a[mt][2], a[mt][3]);
            }
#pragma unroll
            for (int bt = 0; bt < 2; ++bt) {
                const int row = rB + bt * 16;
                ldsm4(Bs + row * 128 + (((k16 * 2 + uB) ^ (row & 7)) << 4),
                      b4[bt][0], b4[bt][1], b4[bt][2], b4[bt][3]);
            }
#pragma unroll
            for (int mt = 0; mt < 4; ++mt)
#pragma unroll
                for (int nt = 0; nt < 4; ++nt)
                    mma16816(acc[mt][nt], a[mt], b4[nt >> 1][(nt & 1) * 2], b4[nt >> 1][(nt & 1) * 2 + 1]);
        }
        __syncthreads();
    }

    // epilogue: bias + relu -> d_y
#pragma unroll
    for (int mt = 0; mt < 4; ++mt) {
        const int r0 = wm * 64 + mt * 16 + (lane >> 2);
#pragma unroll
        for (int half = 0; half < 2; ++half) {
            const int r = r0 + half * 8;
            const int xxo = r & 63, yy = r >> 6;
            if (xxo < 1 || xxo > 48) continue;
            float* base = d_y + (size_t)zc * HW + (size_t)(y0 + yy) * 48 + (xxo - 1);
#pragma unroll
            for (int nt = 0; nt < 4; ++nt) {
                const int n0 = wn * 32 + nt * 8 + (lane & 3) * 2;
                const float bA = __ldg(&b0g[n0]);
                const float bB = __ldg(&b0g[n0 + 1]);
                base[(size_t)n0 * DHW]       = fmaxf(acc[mt][nt][half * 2 + 0] + bA, 0.f);
                base[(size_t)(n0 + 1) * DHW] = fmaxf(acc[mt][nt][half * 2 + 1] + bB, 0.f);
            }
        }
    }
}

// ---------------- InstanceNorm stats ----------------
__global__ void __launch_bounds__(256) stats_kernel() {
    const int c = blockIdx.x;
    const int tid = threadIdx.x;
    const float* src = &d_y[c * DHW];
    float s = 0.f, s2 = 0.f;
    for (int i = tid; i < DHW; i += 256) { float v = src[i]; s += v; s2 += v * v; }
    __shared__ float rs[256], rs2[256];
    rs[tid] = s; rs2[tid] = s2;
    __syncthreads();
    for (int o = 128; o > 0; o >>= 1) {
        if (tid < o) { rs[tid] += rs[tid + o]; rs2[tid] += rs2[tid + o]; }
        __syncthreads();
    }
    if (tid == 0) {
        float mean = rs[0] * (1.0f / (float)DHW);
        float var  = rs2[0] * (1.0f / (float)DHW) - mean * mean;
        d_mean[c] = mean;
        d_rstd[c] = rsqrtf(var + 1e-5f);
    }
}

// ---------------- keypoint sampling ----------------
__global__ void __launch_bounds__(128) sample_kernel(const float* __restrict__ kpts) {
    const int n = blockIdx.x;
    const int c = threadIdx.x;
    __shared__ float pt[3];
    if (c < 3) pt[c] = kpts[n * 3 + c];
    __syncthreads();
    const float ix = (pt[0] + 1.0f) * 0.5f * 47.0f;
    const float iy = (pt[1] + 1.0f) * 0.5f * 47.0f;
    const float iz = (pt[2] + 1.0f) * 0.5f * 47.0f;
    const float x0f = floorf(ix), y0f = floorf(iy), z0f = floorf(iz);
    const float wx = ix - x0f, wy = iy - y0f, wz = iz - z0f;
    int x0 = min(max((int)x0f, 0), 47);
    int y0 = min(max((int)y0f, 0), 47);
    int z0 = min(max((int)z0f, 0), 47);
    int x1 = min(x0 + 1, 47), y1 = min(y0 + 1, 47), z1 = min(z0 + 1, 47);
    const float* vol = &d_y[c * DHW];
    float c000 = vol[z0*HW + y0*48 + x0], c001 = vol[z0*HW + y0*48 + x1];
    float c010 = vol[z0*HW + y1*48 + x0], c011 = vol[z0*HW + y1*48 + x1];
    float c100 = vol[z1*HW + y0*48 + x0], c101 = vol[z1*HW + y0*48 + x1];
    float c110 = vol[z1*HW + y1*48 + x0], c111 = vol[z1*HW + y1*48 + x1];
    float v = c000*((1-wz)*(1-wy)*(1-wx)) + c001*((1-wz)*(1-wy)*wx)
            + c010*((1-wz)*wy*(1-wx))     + c011*((1-wz)*wy*wx)
            + c100*(wz*(1-wy)*(1-wx))     + c101*(wz*(1-wy)*wx)
            + c110*(wz*wy*(1-wx))         + c111*(wz*wy*wx);
    float f = (v - d_mean[c]) * d_rstd[c];
    d_fk2[n * 128 + c] = 2.0f * LOG2E * f;
    __shared__ float red[128];
    red[c] = f * f;
    __syncthreads();
    for (int o = 64; o > 0; o >>= 1) {
        if (c < o) red[c] += red[c + o];
        __syncthreads();
    }
    if (c == 0) d_nn[n] = LOG2E * red[0];
}

// ---------------- softmax interpolation ----------------
__global__ void __launch_bounds__(256) softmax_disp_kernel(const float* __restrict__ disp,
                                                           float* __restrict__ out) {
    __shared__ __align__(16) float fgs[128 * 32];
    __shared__ __align__(16) float fks[32 * 128];
    __shared__ float nns[32];
    __shared__ float dsm[NK * 3];
    const int tid = threadIdx.x;
    const int g0 = blockIdx.x * 32;
    const int g = tid & 31;
    const int q = tid >> 5;
    for (int i = tid; i < 4096; i += 256) {
        int c = i >> 5, gg = i & 31;
        fgs[i] = (d_y[c * DHW + g0 + gg] - d_mean[c]) * d_rstd[c];
    }
    for (int i = tid; i < NK * 3; i += 256) dsm[i] = disp[i];
    float m = -1e30f, S = 0.f, Wx = 0.f, Wy = 0.f, Wz = 0.f;
    for (int ch = 0; ch < 16; ++ch) {
        __syncthreads();
        const float* fsrc = &d_fk2[ch * 4096];
        for (int i = tid; i < 4096; i += 256) fks[i] = fsrc[i];
        if (tid < 32) nns[tid] = d_nn[ch * 32 + tid];
        __syncthreads();
        const int nl0 = q * 4;
        float a0 = -nns[nl0+0], a1 = -nns[nl0+1], a2 = -nns[nl0+2], a3 = -nns[nl0+3];
        const float* k0p = &fks[(nl0+0)*128];
        const float* k1p = &fks[(nl0+1)*128];
        const float* k2p = &fks[(nl0+2)*128];
        const float* k3p = &fks[(nl0+3)*128];
#pragma unroll 8
        for (int c = 0; c < 128; c += 4) {
            float f0 = fgs[(c+0)*32+g], f1 = fgs[(c+1)*32+g];
            float f2 = fgs[(c+2)*32+g], f3 = fgs[(c+3)*32+g];
            float4 k0 = *reinterpret_cast<const float4*>(k0p + c);
            float4 k1 = *reinterpret_cast<const float4*>(k1p + c);
            float4 k2 = *reinterpret_cast<const float4*>(k2p + c);
            float4 k3 = *reinterpret_cast<const float4*>(k3p + c);
            a0 = fmaf(f0,k0.x,a0); a0 = fmaf(f1,k0.y,a0); a0 = fmaf(f2,k0.z,a0); a0 = fmaf(f3,k0.w,a0);
            a1 = fmaf(f0,k1.x,a1); a1 = fmaf(f1,k1.y,a1); a1 = fmaf(f2,k1.z,a1); a1 = fmaf(f3,k1.w,a1);
            a2 = fmaf(f0,k2.x,a2); a2 = fmaf(f1,k2.y,a2); a2 = fmaf(f2,k2.z,a2); a2 = fmaf(f3,k2.w,a2);
            a3 = fmaf(f0,k3.x,a3); a3 = fmaf(f1,k3.y,a3); a3 = fmaf(f2,k3.z,a3); a3 = fmaf(f3,k3.w,a3);
        }
        float m8 = fmaxf(fmaxf(a0,a1), fmaxf(a2,a3));
        if (m8 > m) {
            float cs = exp2a(m - m8);
            S *= cs; Wx *= cs; Wy *= cs; Wz *= cs;
            m = m8;
        }
        const int nb = (ch * 32 + nl0) * 3;
        float e0 = exp2a(a0-m), e1 = exp2a(a1-m), e2 = exp2a(a2-m), e3 = exp2a(a3-m);
        S += e0 + e1 + e2 + e3;
        Wx = fmaf(e0,dsm[nb+0], fmaf(e1,dsm[nb+3], fmaf(e2,dsm[nb+6], fmaf(e3,dsm[nb+9],  Wx))));
        Wy = fmaf(e0,dsm[nb+1], fmaf(e1,dsm[nb+4], fmaf(e2,dsm[nb+7], fmaf(e3,dsm[nb+10], Wy))));
        Wz = fmaf(e0,dsm[nb+2], fmaf(e1,dsm[nb+5], fmaf(e2,dsm[nb+8], fmaf(e3,dsm[nb+11], Wz))));
    }
    __syncthreads();
    float* red = fks;
    red[tid] = m; red[256+tid] = S; red[512+tid] = Wx; red[768+tid] = Wy; red[1024+tid] = Wz;
    __syncthreads();
    if (tid < 32) {
        float mm = -1e30f;
#pragma unroll
        for (int qq = 0; qq < 8; qq++) mm = fmaxf(mm, red[qq*32+tid]);
        float Ss = 0.f, Sx = 0.f, Sy = 0.f, Sz = 0.f;
#pragma unroll
        for (int qq = 0; qq < 8; qq++) {
            float cs = exp2a(red[qq*32+tid] - mm);
            Ss = fmaf(red[256+qq*32+tid], cs, Ss);
            Sx = fmaf(red[512+qq*32+tid], cs, Sx);
            Sy = fmaf(red[768+qq*32+tid], cs, Sy);
            Sz = fmaf(red[1024+qq*32+tid], cs, Sz);
        }
        float inv = 1.0f / Ss;
        out[0*DHW + g0 + tid] = Sx * inv;
        out[1*DHW + g0 + tid] = Sy * inv;
        out[2*DHW + g0 + tid] = Sz * inv;
    }
}

// ---------------- launch ----------------
extern "C" void kernel_launch(void* const* d_in, const int* in_sizes, int n_in,
                              void* d_out, int out_size) {
    const float* kpts  = (const float*)d_in[0];
    const float* disp  = (const float*)d_in[1];
    const float* feats = (const float*)d_in[2];
    const float* W0    = (const float*)d_in[3];
    const float* b0    = (const float*)d_in[4];
    float* out = (float*)d_out;

    static int attr_done = 0;
    if (!attr_done) {
        cudaFuncSetAttribute(conv_mma_kernel, cudaFuncAttributeMaxDynamicSharedMemorySize, CONV_SMEM);
        attr_done = 1;
    }

    convA_kernel<<<2500, 256>>>(feats);
    convW_kernel<<<5184, 256>>>(W0);
    conv_mma_kernel<<<dim3(48, 12), 512, CONV_SMEM>>>(b0);
    stats_kernel<<<128, 256>>>();
    sample_kernel<<<NK, 128>>>(kpts);
    softmax_disp_kernel<<<DHW / 32, 256>>>(disp, out);
}

// round 5
// speedup vs baseline: 2.2851x; 1.3740x over previous
#include <cuda_runtime.h>
#include <cuda_bf16.h>
#include <cstdint>

#define DD   48
#define HW   2304
#define DHW  110592
#define NK   512
#define LOG2E 1.4426950408889634f
#define NSTEPS 162

// ---------------- device scratch ----------------
__device__ __nv_bfloat16 d_xv[160002 * 256];          // padded split-bf16 input (+1-pos guard)
__device__ __nv_bfloat16 d_wb[27 * 128 * 384];        // conv weights [tap][co][bhi|bhi|blo]
__device__ __align__(16) __nv_bfloat16 d_fkb[16 * 12288]; // keypoint feats, pre-swizzled [chunk16][panel6][row32][128B]
__device__ float d_y[128 * DHW];
__device__ float d_mean[128];
__device__ float d_rstd[128];
__device__ float d_nn[NK];

__device__ __forceinline__ float exp2a(float x) {
    float r; asm("ex2.approx.ftz.f32 %0, %1;" : "=f"(r) : "f"(x)); return r;
}
__device__ __forceinline__ uint32_t smem_u32(const void* p) {
    uint32_t a;
    asm("{ .reg .u64 t; cvta.to.shared.u64 t, %1; cvt.u32.u64 %0, t; }" : "=r"(a) : "l"(p));
    return a;
}
__device__ __forceinline__ void cp16(uint32_t dst, const void* src) {
    asm volatile("cp.async.cg.shared.global [%0], [%1], 16;" :: "r"(dst), "l"(src));
}
__device__ __forceinline__ void cp_commit() { asm volatile("cp.async.commit_group;"); }
__device__ __forceinline__ void ldsm4(uint32_t addr, uint32_t& r0, uint32_t& r1, uint32_t& r2, uint32_t& r3) {
    asm volatile("ldmatrix.sync.aligned.m8n8.x4.shared.b16 {%0,%1,%2,%3}, [%4];"
                 : "=r"(r0), "=r"(r1), "=r"(r2), "=r"(r3) : "r"(addr));
}
__device__ __forceinline__ void mma16816(float* c, const uint32_t* a, uint32_t b0, uint32_t b1) {
    asm volatile("mma.sync.aligned.m16n8k16.row.col.f32.bf16.bf16.f32 "
                 "{%0,%1,%2,%3}, {%4,%5,%6,%7}, {%8,%9}, {%0,%1,%2,%3};"
                 : "+f"(c[0]), "+f"(c[1]), "+f"(c[2]), "+f"(c[3])
                 : "r"(a[0]), "r"(a[1]), "r"(a[2]), "r"(a[3]), "r"(b0), "r"(b1));
}

// ---------------- pack input: padded [z50][y50][x64][hi128|lo128], +1 pos guard ----------------
__global__ void __launch_bounds__(256) convA_kernel(const float* __restrict__ feats) {
    __shared__ __nv_bfloat16 tb[64][264];
    const int r = blockIdx.x;
    const int zs = r / 50, ys = r % 50;
    const int zi = zs - 1, yi = ys - 1;
    const int tid = threadIdx.x;
    const int x = tid & 63, cq = tid >> 6;
    const int xi = x - 1;
    const bool rowok = (zi >= 0 && zi < 48 && yi >= 0 && yi < 48);
    const bool xok = rowok && (xi >= 0 && xi < 48);
#pragma unroll 4
    for (int i = 0; i < 32; ++i) {
        int c = cq * 32 + i;
        float v = 0.f;
        if (xok) {
            if (c < 125)       v = feats[c * DHW + zi * HW + yi * 48 + xi];
            else if (c == 125) v = (2.0f / 47.0f) * (float)xi - 1.0f;
            else if (c == 126) v = (2.0f / 47.0f) * (float)yi - 1.0f;
            else               v = (2.0f / 47.0f) * (float)zi - 1.0f;
        }
        __nv_bfloat16 hi = __float2bfloat16(v);
        tb[x][c] = hi;
        tb[x][128 + c] = __float2bfloat16(v - __bfloat162float(hi));
    }
    __syncthreads();
#pragma unroll
    for (int i = 0; i < 8; ++i) {
        int idx = i * 256 + tid;
        int xr = idx >> 5, k8 = idx & 31;
        float4 val = *(const float4*)&tb[xr][k8 * 8];
        *(float4*)(d_xv + (size_t)(r * 64 + xr + 1) * 256 + k8 * 8) = val;
    }
}

// ---------------- pack conv weights ----------------
__global__ void __launch_bounds__(256) convW_kernel(const float* __restrict__ W0) {
    int idx = blockIdx.x * 256 + threadIdx.x;
    int kk = idx % 384;
    int co = (idx / 384) & 127;
    int tap = idx / (384 * 128);
    int cin = kk & 127;
    float v = W0[co * 3456 + cin * 27 + tap];
    __nv_bfloat16 hi = __float2bfloat16(v);
    d_wb[idx] = (kk < 256) ? hi : __float2bfloat16(v - __bfloat162float(hi));
}

// ---------------- conv3d via mma.sync bf16, 3-stage cp.async pipeline ----------------
#define STG_SZ 49152
#define CONV_SMEM (3 * STG_SZ)

__global__ void __launch_bounds__(512, 1) conv_mma_kernel(const float* __restrict__ b0g) {
    extern __shared__ char smem[];
    const uint32_t sb = smem_u32(smem);
    const int tid = threadIdx.x;
    const int zc = blockIdx.x;
    const int y0 = blockIdx.y * 4;

    const int xx = tid >> 3;
    const int u  = tid & 7;
    const uint32_t dstA0 = sb + xx * 128 + ((u ^ (xx & 7)) << 4);
    const uint32_t dstB0 = sb + 32768 + xx * 128 + ((u ^ (xx & 7)) << 4);
    static const int koA_t[6] = {0, 64, 128, 192, 0, 64};

    auto load_stage = [&](int buf, int tap, int s) {
        const int dz = tap / 9;
        const int dyv = (tap % 9) / 3, dx = tap % 3;
        const int koA = koA_t[s];
        const size_t e0 = ((size_t)((zc + dz) * 50 + y0 + dyv) * 64 + xx + dx) * 256 + koA + u * 8;
        const __nv_bfloat16* asrc = d_xv + e0;
        uint32_t ad = dstA0 + buf * STG_SZ;
#pragma unroll
        for (int i = 0; i < 4; ++i)
            cp16(ad + i * 8192, asrc + (size_t)i * 16384);
        const __nv_bfloat16* bsrc = d_wb + (size_t)tap * 49152 + (size_t)xx * 384 + s * 64 + u * 8;
        uint32_t bd = dstB0 + buf * STG_SZ;
#pragma unroll
        for (int i = 0; i < 2; ++i)
            cp16(bd + i * 8192, bsrc + (size_t)i * 64 * 384);
        cp_commit();
    };

    load_stage(0, 0, 0);
    load_stage(1, 0, 1);

    const int wid = tid >> 5, lane = tid & 31;
    const int wm = wid >> 2, wn = wid & 3;
    const int rA = wm * 64 + (lane & 15);
    const int uA = lane >> 4;
    const int rB = wn * 32 + ((lane >> 4) << 3) + (lane & 7);
    const int uB = (lane >> 3) & 1;

    float acc[4][4][4];
#pragma unroll
    for (int i = 0; i < 4; ++i)
#pragma unroll
        for (int j = 0; j < 4; ++j)
#pragma unroll
            for (int k = 0; k < 4; ++k) acc[i][j][k] = 0.f;

    for (int step = 0; step < NSTEPS; ++step) {
        if (step < NSTEPS - 1) asm volatile("cp.async.wait_group 1;");
        else                   asm volatile("cp.async.wait_group 0;");
        __syncthreads();
        const int next = step + 2;
        if (next < NSTEPS) load_stage(next % 3, next / 6, next % 6);

        const uint32_t As = sb + (step % 3) * STG_SZ;
        const uint32_t Bs = As + 32768;
#pragma unroll
        for (int k16 = 0; k16 < 4; ++k16) {
            uint32_t a[4][4], b4[2][4];
#pragma unroll
            for (int mt = 0; mt < 4; ++mt) {
                const int row = rA + mt * 16;
                ldsm4(As + row * 128 + (((k16 * 2 + uA) ^ (row & 7)) << 4),
                      a[mt][0], a[mt][1], a[mt][2], a[mt][3]);
            }
#pragma unroll
            for (int bt = 0; bt < 2; ++bt) {
                const int row = rB + bt * 16;
                ldsm4(Bs + row * 128 + (((k16 * 2 + uB) ^ (row & 7)) << 4),
                      b4[bt][0], b4[bt][1], b4[bt][2], b4[bt][3]);
            }
#pragma unroll
            for (int mt = 0; mt < 4; ++mt)
#pragma unroll
                for (int nt = 0; nt < 4; ++nt)
                    mma16816(acc[mt][nt], a[mt], b4[nt >> 1][(nt & 1) * 2], b4[nt >> 1][(nt & 1) * 2 + 1]);
        }
        __syncthreads();
    }

#pragma unroll
    for (int mt = 0; mt < 4; ++mt) {
        const int r0 = wm * 64 + mt * 16 + (lane >> 2);
#pragma unroll
        for (int half = 0; half < 2; ++half) {
            const int r = r0 + half * 8;
            const int xxo = r & 63, yy = r >> 6;
            if (xxo < 1 || xxo > 48) continue;
            float* base = d_y + (size_t)zc * HW + (size_t)(y0 + yy) * 48 + (xxo - 1);
#pragma unroll
            for (int nt = 0; nt < 4; ++nt) {
                const int n0 = wn * 32 + nt * 8 + (lane & 3) * 2;
                const float bA = __ldg(&b0g[n0]);
                const float bB = __ldg(&b0g[n0 + 1]);
                base[(size_t)n0 * DHW]       = fmaxf(acc[mt][nt][half * 2 + 0] + bA, 0.f);
                base[(size_t)(n0 + 1) * DHW] = fmaxf(acc[mt][nt][half * 2 + 1] + bB, 0.f);
            }
        }
    }
}

// ---------------- InstanceNorm stats (float4) ----------------
__global__ void __launch_bounds__(256) stats_kernel() {
    const int c = blockIdx.x;
    const int tid = threadIdx.x;
    const float4* src4 = (const float4*)&d_y[(size_t)c * DHW];
    float s = 0.f, s2 = 0.f;
    for (int i = tid; i < DHW / 4; i += 256) {
        float4 v = src4[i];
        s  += v.x + v.y + v.z + v.w;
        s2 += v.x * v.x + v.y * v.y + v.z * v.z + v.w * v.w;
    }
    __shared__ float rs[256], rs2[256];
    rs[tid] = s; rs2[tid] = s2;
    __syncthreads();
    for (int o = 128; o > 0; o >>= 1) {
        if (tid < o) { rs[tid] += rs[tid + o]; rs2[tid] += rs2[tid + o]; }
        __syncthreads();
    }
    if (tid == 0) {
        float mean = rs[0] * (1.0f / (float)DHW);
        float var  = rs2[0] * (1.0f / (float)DHW) - mean * mean;
        d_mean[c] = mean;
        d_rstd[c] = rsqrtf(var + 1e-5f);
    }
}

// ---------------- keypoint sampling: writes pre-swizzled split-bf16 B + norms ----------------
__global__ void __launch_bounds__(128) sample_kernel(const float* __restrict__ kpts) {
    const int n = blockIdx.x;
    const int c = threadIdx.x;
    __shared__ float pt[3];
    if (c < 3) pt[c] = kpts[n * 3 + c];
    __syncthreads();
    const float ix = (pt[0] + 1.0f) * 0.5f * 47.0f;
    const float iy = (pt[1] + 1.0f) * 0.5f * 47.0f;
    const float iz = (pt[2] + 1.0f) * 0.5f * 47.0f;
    const float x0f = floorf(ix), y0f = floorf(iy), z0f = floorf(iz);
    const float wx = ix - x0f, wy = iy - y0f, wz = iz - z0f;
    int x0 = min(max((int)x0f, 0), 47);
    int y0 = min(max((int)y0f, 0), 47);
    int z0 = min(max((int)z0f, 0), 47);
    int x1 = min(x0 + 1, 47), y1 = min(y0 + 1, 47), z1 = min(z0 + 1, 47);
    const float* vol = &d_y[(size_t)c * DHW];
    float c000 = vol[z0*HW + y0*48 + x0], c001 = vol[z0*HW + y0*48 + x1];
    float c010 = vol[z0*HW + y1*48 + x0], c011 = vol[z0*HW + y1*48 + x1];
    float c100 = vol[z1*HW + y0*48 + x0], c101 = vol[z1*HW + y0*48 + x1];
    float c110 = vol[z1*HW + y1*48 + x0], c111 = vol[z1*HW + y1*48 + x1];
    float v = c000*((1-wz)*(1-wy)*(1-wx)) + c001*((1-wz)*(1-wy)*wx)
            + c010*((1-wz)*wy*(1-wx))     + c011*((1-wz)*wy*wx)
            + c100*(wz*(1-wy)*(1-wx))     + c101*(wz*(1-wy)*wx)
            + c110*(wz*wy*(1-wx))         + c111*(wz*wy*wx);
    float f = (v - d_mean[c]) * d_rstd[c];

    // b = 2*log2e*f, split-bf16, write to pre-swizzled panels: [bhi|bhi|blo]
    float b = 2.0f * LOG2E * f;
    __nv_bfloat16 bh = __float2bfloat16(b);
    __nv_bfloat16 bl = __float2bfloat16(b - __bfloat162float(bh));
    const int chunk = n >> 5, row = n & 31;
    const int u = (c & 63) >> 3, j = c & 7, ph = c >> 6;
    char* fb = (char*)d_fkb;
    size_t base = (size_t)chunk * 24576 + (size_t)row * 128 + ((u ^ (row & 7)) << 4) + j * 2;
    *(__nv_bfloat16*)(fb + base + (0 + ph) * 4096) = bh;
    *(__nv_bfloat16*)(fb + base + (2 + ph) * 4096) = bh;
    *(__nv_bfloat16*)(fb + base + (4 + ph) * 4096) = bl;

    __shared__ float red[128];
    red[c] = f * f;
    __syncthreads();
    for (int o = 64; o > 0; o >>= 1) {
        if (c < o) red[c] += red[c + o];
        __syncthreads();
    }
    if (c == 0) d_nn[n] = LOG2E * red[0];
}

// ---------------- softmax interpolation via mma.sync ----------------
// block: 64 voxels, 128 threads (4 warps x m16). K=384 split layout.
// A panels [6][64 rows][128B]: [ahi|alo|ahi]; B chunks (n32): panels [6][32][128B]: [bhi|bhi|blo]
#define SMX_A    0
#define SMX_B    49152
#define SMX_NN   98304
#define SMX_DSM  100352
#define SMX_MEAN 108544
#define SMX_RSTD 109056
#define SMX_TOTAL 109568

__global__ void __launch_bounds__(128, 2) softmax_mma_kernel(const float* __restrict__ disp,
                                                             float* __restrict__ out) {
    extern __shared__ char sm[];
    const uint32_t sb = smem_u32(sm);
    const int tid = threadIdx.x;
    const int g0 = blockIdx.x * 64;

    float* nns = (float*)(sm + SMX_NN);
    float4* dsm4 = (float4*)(sm + SMX_DSM);
    for (int i = tid; i < NK; i += 128) {
        nns[i] = d_nn[i];
        float4 dv;
        dv.x = disp[i * 3]; dv.y = disp[i * 3 + 1]; dv.z = disp[i * 3 + 2]; dv.w = 0.f;
        dsm4[i] = dv;
    }
    ((float*)(sm + SMX_MEAN))[tid & 127] = d_mean[tid & 127];
    ((float*)(sm + SMX_RSTD))[tid & 127] = d_rstd[tid & 127];

    // prefetch B chunk 0
    {
        const char* src = (const char*)d_fkb;
        for (int i = tid; i < 1536; i += 128) cp16(sb + SMX_B + i * 16, src + (size_t)i * 16);
        cp_commit();
    }
    __syncthreads();

    // build A (normalize + split)
    {
        const float* mean = (const float*)(sm + SMX_MEAN);
        const float* rstd = (const float*)(sm + SMX_RSTD);
        const int g = tid & 63, half = tid >> 6;
#pragma unroll
        for (int oct = 0; oct < 8; ++oct) {
            const int c0 = half * 64 + oct * 8;
            union { __nv_bfloat16 h[8]; float4 v; } H, L;
#pragma unroll
            for (int j = 0; j < 8; ++j) {
                float f = d_y[(size_t)(c0 + j) * DHW + g0 + g];
                float a = (f - mean[c0 + j]) * rstd[c0 + j];
                __nv_bfloat16 hh = __float2bfloat16(a);
                H.h[j] = hh;
                L.h[j] = __float2bfloat16(a - __bfloat162float(hh));
            }
            const uint32_t sw = (uint32_t)((oct ^ (g & 7)) << 4);
            char* base = sm + SMX_A + g * 128 + sw;
            *(float4*)(base + (0 + half) * 8192) = H.v;
            *(float4*)(base + (4 + half) * 8192) = H.v;
            *(float4*)(base + (2 + half) * 8192) = L.v;
        }
    }
    __syncthreads();

    const int wid = tid >> 5, lane = tid & 31;
    const int rA = wid * 16 + (lane & 15);
    const int uA = lane >> 4;
    const int rB0 = ((lane >> 4) << 3) + (lane & 7);
    const int uBb = (lane >> 3) & 1;

    float mlo = -1e30f, mhi = -1e30f;
    float Slo = 0.f, Shi = 0.f;
    float Wlo0 = 0.f, Wlo1 = 0.f, Wlo2 = 0.f;
    float Whi0 = 0.f, Whi1 = 0.f, Whi2 = 0.f;

    for (int ci = 0; ci < 16; ++ci) {
        asm volatile("cp.async.wait_group 0;");
        __syncthreads();
        if (ci < 15) {
            const char* src = (const char*)d_fkb + (size_t)(ci + 1) * 24576;
            const uint32_t dst = sb + SMX_B + ((ci + 1) & 1) * 24576;
            for (int i = tid; i < 1536; i += 128) cp16(dst + i * 16, src + (size_t)i * 16);
            cp_commit();
        }
        const uint32_t Bb = sb + SMX_B + (ci & 1) * 24576;
        const int nbase = ci * 32;

        float acc[4][4];
#pragma unroll
        for (int nt = 0; nt < 4; ++nt) {
            float i0 = -nns[nbase + nt * 8 + (lane & 3) * 2];
            float i1 = -nns[nbase + nt * 8 + (lane & 3) * 2 + 1];
            acc[nt][0] = i0; acc[nt][1] = i1; acc[nt][2] = i0; acc[nt][3] = i1;
        }
#pragma unroll
        for (int s = 0; s < 24; ++s) {
            const int pan = s >> 2, inner = s & 3;
            uint32_t a[4];
            ldsm4(sb + SMX_A + pan * 8192 + rA * 128 + (((inner * 2 + uA) ^ (rA & 7)) << 4),
                  a[0], a[1], a[2], a[3]);
            uint32_t b4[2][4];
#pragma unroll
            for (int bt = 0; bt < 2; ++bt) {
                const int row = bt * 16 + rB0;
                ldsm4(Bb + pan * 4096 + row * 128 + (((inner * 2 + uBb) ^ (row & 7)) << 4),
                      b4[bt][0], b4[bt][1], b4[bt][2], b4[bt][3]);
            }
#pragma unroll
            for (int nt = 0; nt < 4; ++nt)
                mma16816(acc[nt], a, b4[nt >> 1][(nt & 1) * 2], b4[nt >> 1][(nt & 1) * 2 + 1]);
        }

        // online softmax update
        float cmlo = fmaxf(fmaxf(fmaxf(acc[0][0], acc[0][1]), fmaxf(acc[1][0], acc[1][1])),
                           fmaxf(fmaxf(acc[2][0], acc[2][1]), fmaxf(acc[3][0], acc[3][1])));
        float cmhi = fmaxf(fmaxf(fmaxf(acc[0][2], acc[0][3]), fmaxf(acc[1][2], acc[1][3])),
                           fmaxf(fmaxf(acc[2][2], acc[2][3]), fmaxf(acc[3][2], acc[3][3])));
        cmlo = fmaxf(cmlo, __shfl_xor_sync(0xffffffffu, cmlo, 1));
        cmlo = fmaxf(cmlo, __shfl_xor_sync(0xffffffffu, cmlo, 2));
        cmhi = fmaxf(cmhi, __shfl_xor_sync(0xffffffffu, cmhi, 1));
        cmhi = fmaxf(cmhi, __shfl_xor_sync(0xffffffffu, cmhi, 2));
        if (cmlo > mlo) {
            float cs = exp2a(mlo - cmlo);
            Slo *= cs; Wlo0 *= cs; Wlo1 *= cs; Wlo2 *= cs;
            mlo = cmlo;
        }
        if (cmhi > mhi) {
            float cs = exp2a(mhi - cmhi);
            Shi *= cs; Whi0 *= cs; Whi1 *= cs; Whi2 *= cs;
            mhi = cmhi;
        }
#pragma unroll
        for (int nt = 0; nt < 4; ++nt) {
#pragma unroll
            for (int j = 0; j < 2; ++j) {
                const float4 dv = dsm4[nbase + nt * 8 + (lane & 3) * 2 + j];
                float elo = exp2a(acc[nt][j] - mlo);
                float ehi = exp2a(acc[nt][2 + j] - mhi);
                Slo += elo; Shi += ehi;
                Wlo0 = fmaf(elo, dv.x, Wlo0); Wlo1 = fmaf(elo, dv.y, Wlo1); Wlo2 = fmaf(elo, dv.z, Wlo2);
                Whi0 = fmaf(ehi, dv.x, Whi0); Whi1 = fmaf(ehi, dv.y, Whi1); Whi2 = fmaf(ehi, dv.z, Whi2);
            }
        }
    }

    // quad reduction (max already synchronized within quads)
#pragma unroll
    for (int d = 1; d <= 2; d <<= 1) {
        Slo += __shfl_xor_sync(0xffffffffu, Slo, d);
        Shi += __shfl_xor_sync(0xffffffffu, Shi, d);
        Wlo0 += __shfl_xor_sync(0xffffffffu, Wlo0, d);
        Wlo1 += __shfl_xor_sync(0xffffffffu, Wlo1, d);
        Wlo2 += __shfl_xor_sync(0xffffffffu, Wlo2, d);
        Whi0 += __shfl_xor_sync(0xffffffffu, Whi0, d);
        Whi1 += __shfl_xor_sync(0xffffffffu, Whi1, d);
        Whi2 += __shfl_xor_sync(0xffffffffu, Whi2, d);
    }
    if ((lane & 3) == 0) {
        const int rlo = g0 + wid * 16 + (lane >> 2);
        const int rhi = rlo + 8;
        const float ilo = 1.0f / Slo, ihi = 1.0f / Shi;
        out[0 * DHW + rlo] = Wlo0 * ilo;
        out[1 * DHW + rlo] = Wlo1 * ilo;
        out[2 * DHW + rlo] = Wlo2 * ilo;
        out[0 * DHW + rhi] = Whi0 * ihi;
        out[1 * DHW + rhi] = Whi1 * ihi;
        out[2 * DHW + rhi] = Whi2 * ihi;
    }
}

// ---------------- launch ----------------
extern "C" void kernel_launch(void* const* d_in, const int* in_sizes, int n_in,
                              void* d_out, int out_size) {
    const float* kpts  = (const float*)d_in[0];
    const float* disp  = (const float*)d_in[1];
    const float* feats = (const float*)d_in[2];
    const float* W0    = (const float*)d_in[3];
    const float* b0    = (const float*)d_in[4];
    float* out = (float*)d_out;

    static int attr_done = 0;
    if (!attr_done) {
        cudaFuncSetAttribute(conv_mma_kernel, cudaFuncAttributeMaxDynamicSharedMemorySize, CONV_SMEM);
        cudaFuncSetAttribute(softmax_mma_kernel, cudaFuncAttributeMaxDynamicSharedMemorySize, SMX_TOTAL);
        attr_done = 1;
    }

    convA_kernel<<<2500, 256>>>(feats);
    convW_kernel<<<5184, 256>>>(W0);
    conv_mma_kernel<<<dim3(48, 12), 512, CONV_SMEM>>>(b0);
    stats_kernel<<<128, 256>>>();
    sample_kernel<<<NK, 128>>>(kpts);
    softmax_mma_kernel<<<DHW / 64, 128, SMX_TOTAL>>>(disp, out);
}

// round 6
// speedup vs baseline: 2.4309x; 1.0638x over previous
#include <cuda_runtime.h>
#include <cuda_bf16.h>
#include <cstdint>

#define DD   48
#define HW   2304
#define DHW  110592
#define NK   512
#define LOG2E 1.4426950408889634f
#define NSTEPS 162

// ---------------- device scratch ----------------
__device__ __nv_bfloat16 d_xv[160002 * 256];          // padded split-bf16 input (+1-pos guard)
__device__ __nv_bfloat16 d_wb[27 * 128 * 384];        // conv weights [tap][co][bhi|bhi|blo]
__device__ __align__(16) __nv_bfloat16 d_fkb[16 * 12288]; // keypoint feats, pre-swizzled
__device__ float d_y[128 * DHW];
__device__ float d_sp[512 * 2];                       // stats partials
__device__ float d_mean[128];
__device__ float d_rstd[128];
__device__ float d_nn[NK];

__device__ __forceinline__ float exp2a(float x) {
    float r; asm("ex2.approx.ftz.f32 %0, %1;" : "=f"(r) : "f"(x)); return r;
}
__device__ __forceinline__ uint32_t smem_u32(const void* p) {
    uint32_t a;
    asm("{ .reg .u64 t; cvta.to.shared.u64 t, %1; cvt.u32.u64 %0, t; }" : "=r"(a) : "l"(p));
    return a;
}
__device__ __forceinline__ void cp16(uint32_t dst, const void* src) {
    asm volatile("cp.async.cg.shared.global [%0], [%1], 16;" :: "r"(dst), "l"(src));
}
__device__ __forceinline__ void cp_commit() { asm volatile("cp.async.commit_group;"); }
__device__ __forceinline__ void ldsm4(uint32_t addr, uint32_t& r0, uint32_t& r1, uint32_t& r2, uint32_t& r3) {
    asm volatile("ldmatrix.sync.aligned.m8n8.x4.shared.b16 {%0,%1,%2,%3}, [%4];"
                 : "=r"(r0), "=r"(r1), "=r"(r2), "=r"(r3) : "r"(addr));
}
__device__ __forceinline__ void mma16816(float* c, const uint32_t* a, uint32_t b0, uint32_t b1) {
    asm volatile("mma.sync.aligned.m16n8k16.row.col.f32.bf16.bf16.f32 "
                 "{%0,%1,%2,%3}, {%4,%5,%6,%7}, {%8,%9}, {%0,%1,%2,%3};"
                 : "+f"(c[0]), "+f"(c[1]), "+f"(c[2]), "+f"(c[3])
                 : "r"(a[0]), "r"(a[1]), "r"(a[2]), "r"(a[3]), "r"(b0), "r"(b1));
}

// ---------------- pack input: padded [z50][y50][x64][hi128|lo128], +1 pos guard ----------------
__global__ void __launch_bounds__(256) convA_kernel(const float* __restrict__ feats) {
    __shared__ __nv_bfloat16 tb[64][264];
    const int r = blockIdx.x;
    const int zs = r / 50, ys = r % 50;
    const int zi = zs - 1, yi = ys - 1;
    const int tid = threadIdx.x;
    const int x = tid & 63, cq = tid >> 6;
    const int xi = x - 1;
    const bool rowok = (zi >= 0 && zi < 48 && yi >= 0 && yi < 48);
    const bool xok = rowok && (xi >= 0 && xi < 48);
#pragma unroll 4
    for (int i = 0; i < 32; ++i) {
        int c = cq * 32 + i;
        float v = 0.f;
        if (xok) {
            if (c < 125)       v = feats[c * DHW + zi * HW + yi * 48 + xi];
            else if (c == 125) v = (2.0f / 47.0f) * (float)xi - 1.0f;
            else if (c == 126) v = (2.0f / 47.0f) * (float)yi - 1.0f;
            else               v = (2.0f / 47.0f) * (float)zi - 1.0f;
        }
        __nv_bfloat16 hi = __float2bfloat16(v);
        tb[x][c] = hi;
        tb[x][128 + c] = __float2bfloat16(v - __bfloat162float(hi));
    }
    __syncthreads();
#pragma unroll
    for (int i = 0; i < 8; ++i) {
        int idx = i * 256 + tid;
        int xr = idx >> 5, k8 = idx & 31;
        float4 val = *(const float4*)&tb[xr][k8 * 8];
        *(float4*)(d_xv + (size_t)(r * 64 + xr + 1) * 256 + k8 * 8) = val;
    }
}

// ---------------- pack conv weights ----------------
__global__ void __launch_bounds__(256) convW_kernel(const float* __restrict__ W0) {
    int idx = blockIdx.x * 256 + threadIdx.x;
    int kk = idx % 384;
    int co = (idx / 384) & 127;
    int tap = idx / (384 * 128);
    int cin = kk & 127;
    float v = W0[co * 3456 + cin * 27 + tap];
    __nv_bfloat16 hi = __float2bfloat16(v);
    d_wb[idx] = (kk < 256) ? hi : __float2bfloat16(v - __bfloat162float(hi));
}

// ---------------- conv3d via mma.sync bf16: 256thr, 2 CTA/SM, 3-stage, 1 sync/step ----------------
#define STG 32768                 // A 16KB + B 16KB
#define CONV_SMEM (3 * STG)

__global__ void __launch_bounds__(256, 2) conv_mma_kernel(const float* __restrict__ b0g) {
    extern __shared__ char smem[];
    const uint32_t sb = smem_u32(smem);
    const int tid = threadIdx.x;
    const int zc = blockIdx.x;        // 0..47
    const int y0 = blockIdx.y * 2;    // 0..46

    static const int koA_t[6] = {0, 64, 128, 192, 0, 64};

    auto load_stage = [&](int buf, int tap, int s) {
        const int dz = tap / 9;
        const int dyv = (tap % 9) / 3, dx = tap % 3;
        const int koA = koA_t[s];
        const uint32_t ab = sb + buf * STG;
#pragma unroll
        for (int i = 0; i < 4; ++i) {
            const int idx = i * 256 + tid;
            const int row = idx >> 3, u = idx & 7;
            const int y = row >> 6, x = row & 63;
            const size_t pos = (size_t)((zc + dz) * 50 + y0 + y + dyv) * 64 + x + dx;
            cp16(ab + row * 128 + ((u ^ (row & 7)) << 4),
                 d_xv + pos * 256 + koA + u * 8);
        }
        const __nv_bfloat16* bsrc = d_wb + (size_t)tap * 49152 + s * 64;
#pragma unroll
        for (int i = 0; i < 4; ++i) {
            const int idx = i * 256 + tid;
            const int row = idx >> 3, u = idx & 7;
            cp16(ab + 16384 + row * 128 + ((u ^ (row & 7)) << 4),
                 bsrc + (size_t)row * 384 + u * 8);
        }
        cp_commit();
    };

    load_stage(0, 0, 0);
    load_stage(1, 0, 1);

    const int wid = tid >> 5, lane = tid & 31;
    const int wm = wid >> 2, wn = wid & 3;
    const int rA = wm * 64 + (lane & 15);
    const int uA = lane >> 4;
    const int rB = wn * 32 + ((lane >> 4) << 3) + (lane & 7);
    const int uB = (lane >> 3) & 1;

    float acc[4][4][4];
#pragma unroll
    for (int i = 0; i < 4; ++i)
#pragma unroll
        for (int j = 0; j < 4; ++j)
#pragma unroll
            for (int k = 0; k < 4; ++k) acc[i][j][k] = 0.f;

    for (int step = 0; step < NSTEPS; ++step) {
        if (step < NSTEPS - 1) asm volatile("cp.async.wait_group 1;");
        else                   asm volatile("cp.async.wait_group 0;");
        __syncthreads();
        const int next = step + 2;
        if (next < NSTEPS) load_stage(next % 3, next / 6, next % 6);

        const uint32_t As = sb + (step % 3) * STG;
        const uint32_t Bs = As + 16384;
#pragma unroll
        for (int k16 = 0; k16 < 4; ++k16) {
            uint32_t a[4][4], b4[2][4];
#pragma unroll
            for (int mt = 0; mt < 4; ++mt) {
                const int row = rA + mt * 16;
                ldsm4(As + row * 128 + (((k16 * 2 + uA) ^ (row & 7)) << 4),
                      a[mt][0], a[mt][1], a[mt][2], a[mt][3]);
            }
#pragma unroll
            for (int bt = 0; bt < 2; ++bt) {
                const int row = rB + bt * 16;
                ldsm4(Bs + row * 128 + (((k16 * 2 + uB) ^ (row & 7)) << 4),
                      b4[bt][0], b4[bt][1], b4[bt][2], b4[bt][3]);
            }
#pragma unroll
            for (int mt = 0; mt < 4; ++mt)
#pragma unroll
                for (int nt = 0; nt < 4; ++nt)
                    mma16816(acc[mt][nt], a[mt], b4[nt >> 1][(nt & 1) * 2], b4[nt >> 1][(nt & 1) * 2 + 1]);
        }
    }

#pragma unroll
    for (int mt = 0; mt < 4; ++mt) {
        const int r0 = wm * 64 + mt * 16 + (lane >> 2);
#pragma unroll
        for (int half = 0; half < 2; ++half) {
            const int r = r0 + half * 8;
            const int xxo = r & 63, yy = r >> 6;
            if (xxo < 1 || xxo > 48) continue;
            float* base = d_y + (size_t)zc * HW + (size_t)(y0 + yy) * 48 + (xxo - 1);
#pragma unroll
            for (int nt = 0; nt < 4; ++nt) {
                const int n0 = wn * 32 + nt * 8 + (lane & 3) * 2;
                const float bA = __ldg(&b0g[n0]);
                const float bB = __ldg(&b0g[n0 + 1]);
                base[(size_t)n0 * DHW]       = fmaxf(acc[mt][nt][half * 2 + 0] + bA, 0.f);
                base[(size_t)(n0 + 1) * DHW] = fmaxf(acc[mt][nt][half * 2 + 1] + bB, 0.f);
            }
        }
    }
}

// ---------------- InstanceNorm stats: partials then finalize ----------------
__global__ void __launch_bounds__(256) stats_part_kernel() {
    const int c = blockIdx.x >> 2, part = blockIdx.x & 3;
    const int tid = threadIdx.x;
    const float4* src4 = (const float4*)&d_y[(size_t)c * DHW] + part * 6912;
    float s = 0.f, s2 = 0.f;
    for (int i = tid; i < 6912; i += 256) {
        float4 v = src4[i];
        s  += v.x + v.y + v.z + v.w;
        s2 += v.x * v.x + v.y * v.y + v.z * v.z + v.w * v.w;
    }
#pragma unroll
    for (int o = 16; o > 0; o >>= 1) {
        s  += __shfl_xor_sync(0xffffffffu, s, o);
        s2 += __shfl_xor_sync(0xffffffffu, s2, o);
    }
    __shared__ float rs[8], rs2[8];
    if ((tid & 31) == 0) { rs[tid >> 5] = s; rs2[tid >> 5] = s2; }
    __syncthreads();
    if (tid == 0) {
        float S = 0.f, S2 = 0.f;
#pragma unroll
        for (int i = 0; i < 8; ++i) { S += rs[i]; S2 += rs2[i]; }
        d_sp[blockIdx.x * 2] = S;
        d_sp[blockIdx.x * 2 + 1] = S2;
    }
}
__global__ void __launch_bounds__(128) stats_fin_kernel() {
    const int c = threadIdx.x;
    float S = 0.f, S2 = 0.f;
#pragma unroll
    for (int p = 0; p < 4; ++p) {
        S  += d_sp[(c * 4 + p) * 2];
        S2 += d_sp[(c * 4 + p) * 2 + 1];
    }
    float mean = S * (1.0f / (float)DHW);
    float var  = S2 * (1.0f / (float)DHW) - mean * mean;
    d_mean[c] = mean;
    d_rstd[c] = rsqrtf(var + 1e-5f);
}

// ---------------- keypoint sampling: writes pre-swizzled split-bf16 B + norms ----------------
__global__ void __launch_bounds__(128) sample_kernel(const float* __restrict__ kpts) {
    const int n = blockIdx.x;
    const int c = threadIdx.x;
    __shared__ float pt[3];
    if (c < 3) pt[c] = kpts[n * 3 + c];
    __syncthreads();
    const float ix = (pt[0] + 1.0f) * 0.5f * 47.0f;
    const float iy = (pt[1] + 1.0f) * 0.5f * 47.0f;
    const float iz = (pt[2] + 1.0f) * 0.5f * 47.0f;
    const float x0f = floorf(ix), y0f = floorf(iy), z0f = floorf(iz);
    const float wx = ix - x0f, wy = iy - y0f, wz = iz - z0f;
    int x0 = min(max((int)x0f, 0), 47);
    int y0 = min(max((int)y0f, 0), 47);
    int z0 = min(max((int)z0f, 0), 47);
    int x1 = min(x0 + 1, 47), y1 = min(y0 + 1, 47), z1 = min(z0 + 1, 47);
    const float* vol = &d_y[(size_t)c * DHW];
    float c000 = vol[z0*HW + y0*48 + x0], c001 = vol[z0*HW + y0*48 + x1];
    float c010 = vol[z0*HW + y1*48 + x0], c011 = vol[z0*HW + y1*48 + x1];
    float c100 = vol[z1*HW + y0*48 + x0], c101 = vol[z1*HW + y0*48 + x1];
    float c110 = vol[z1*HW + y1*48 + x0], c111 = vol[z1*HW + y1*48 + x1];
    float v = c000*((1-wz)*(1-wy)*(1-wx)) + c001*((1-wz)*(1-wy)*wx)
            + c010*((1-wz)*wy*(1-wx))     + c011*((1-wz)*wy*wx)
            + c100*(wz*(1-wy)*(1-wx))     + c101*(wz*(1-wy)*wx)
            + c110*(wz*wy*(1-wx))         + c111*(wz*wy*wx);
    float f = (v - d_mean[c]) * d_rstd[c];

    float b = 2.0f * LOG2E * f;
    __nv_bfloat16 bh = __float2bfloat16(b);
    __nv_bfloat16 bl = __float2bfloat16(b - __bfloat162float(bh));
    const int chunk = n >> 5, row = n & 31;
    const int u = (c & 63) >> 3, j = c & 7, ph = c >> 6;
    char* fb = (char*)d_fkb;
    size_t base = (size_t)chunk * 24576 + (size_t)row * 128 + ((u ^ (row & 7)) << 4) + j * 2;
    *(__nv_bfloat16*)(fb + base + (0 + ph) * 4096) = bh;
    *(__nv_bfloat16*)(fb + base + (2 + ph) * 4096) = bh;
    *(__nv_bfloat16*)(fb + base + (4 + ph) * 4096) = bl;

    __shared__ float red[128];
    red[c] = f * f;
    __syncthreads();
    for (int o = 64; o > 0; o >>= 1) {
        if (c < o) red[c] += red[c + o];
        __syncthreads();
    }
    if (c == 0) d_nn[n] = LOG2E * red[0];
}

// ---------------- softmax interpolation via mma.sync ----------------
#define SMX_A    0
#define SMX_B    49152
#define SMX_NN   98304
#define SMX_DSM  100352
#define SMX_MEAN 108544
#define SMX_RSTD 109056
#define SMX_TOTAL 109568

__global__ void __launch_bounds__(128, 2) softmax_mma_kernel(const float* __restrict__ disp,
                                                             float* __restrict__ out) {
    extern __shared__ char sm[];
    const uint32_t sb = smem_u32(sm);
    const int tid = threadIdx.x;
    const int g0 = blockIdx.x * 64;

    float* nns = (float*)(sm + SMX_NN);
    float4* dsm4 = (float4*)(sm + SMX_DSM);
    for (int i = tid; i < NK; i += 128) {
        nns[i] = d_nn[i];
        float4 dv;
        dv.x = disp[i * 3]; dv.y = disp[i * 3 + 1]; dv.z = disp[i * 3 + 2]; dv.w = 0.f;
        dsm4[i] = dv;
    }
    ((float*)(sm + SMX_MEAN))[tid & 127] = d_mean[tid & 127];
    ((float*)(sm + SMX_RSTD))[tid & 127] = d_rstd[tid & 127];

    {
        const char* src = (const char*)d_fkb;
        for (int i = tid; i < 1536; i += 128) cp16(sb + SMX_B + i * 16, src + (size_t)i * 16);
        cp_commit();
    }
    __syncthreads();

    {
        const float* mean = (const float*)(sm + SMX_MEAN);
        const float* rstd = (const float*)(sm + SMX_RSTD);
        const int g = tid & 63, half = tid >> 6;
#pragma unroll
        for (int oct = 0; oct < 8; ++oct) {
            const int c0 = half * 64 + oct * 8;
            union { __nv_bfloat16 h[8]; float4 v; } H, L;
#pragma unroll
            for (int j = 0; j < 8; ++j) {
                float f = d_y[(size_t)(c0 + j) * DHW + g0 + g];
                float a = (f - mean[c0 + j]) * rstd[c0 + j];
                __nv_bfloat16 hh = __float2bfloat16(a);
                H.h[j] = hh;
                L.h[j] = __float2bfloat16(a - __bfloat162float(hh));
            }
            const uint32_t sw = (uint32_t)((oct ^ (g & 7)) << 4);
            char* base = sm + SMX_A + g * 128 + sw;
            *(float4*)(base + (0 + half) * 8192) = H.v;
            *(float4*)(base + (4 + half) * 8192) = H.v;
            *(float4*)(base + (2 + half) * 8192) = L.v;
        }
    }
    __syncthreads();

    const int wid = tid >> 5, lane = tid & 31;
    const int rA = wid * 16 + (lane & 15);
    const int uA = lane >> 4;
    const int rB0 = ((lane >> 4) << 3) + (lane & 7);
    const int uBb = (lane >> 3) & 1;

    float mlo = -1e30f, mhi = -1e30f;
    float Slo = 0.f, Shi = 0.f;
    float Wlo0 = 0.f, Wlo1 = 0.f, Wlo2 = 0.f;
    float Whi0 = 0.f, Whi1 = 0.f, Whi2 = 0.f;

    for (int ci = 0; ci < 16; ++ci) {
        asm volatile("cp.async.wait_group 0;");
        __syncthreads();
        if (ci < 15) {
            const char* src = (const char*)d_fkb + (size_t)(ci + 1) * 24576;
            const uint32_t dst = sb + SMX_B + ((ci + 1) & 1) * 24576;
            for (int i = tid; i < 1536; i += 128) cp16(dst + i * 16, src + (size_t)i * 16);
            cp_commit();
        }
        const uint32_t Bb = sb + SMX_B + (ci & 1) * 24576;
        const int nbase = ci * 32;

        float acc[4][4];
#pragma unroll
        for (int nt = 0; nt < 4; ++nt) {
            float i0 = -nns[nbase + nt * 8 + (lane & 3) * 2];
            float i1 = -nns[nbase + nt * 8 + (lane & 3) * 2 + 1];
            acc[nt][0] = i0; acc[nt][1] = i1; acc[nt][2] = i0; acc[nt][3] = i1;
        }
#pragma unroll
        for (int s = 0; s < 24; ++s) {
            const int pan = s >> 2, inner = s & 3;
            uint32_t a[4];
            ldsm4(sb + SMX_A + pan * 8192 + rA * 128 + (((inner * 2 + uA) ^ (rA & 7)) << 4),
                  a[0], a[1], a[2], a[3]);
            uint32_t b4[2][4];
#pragma unroll
            for (int bt = 0; bt < 2; ++bt) {
                const int row = bt * 16 + rB0;
                ldsm4(Bb + pan * 4096 + row * 128 + (((inner * 2 + uBb) ^ (row & 7)) << 4),
                      b4[bt][0], b4[bt][1], b4[bt][2], b4[bt][3]);
            }
#pragma unroll
            for (int nt = 0; nt < 4; ++nt)
                mma16816(acc[nt], a, b4[nt >> 1][(nt & 1) * 2], b4[nt >> 1][(nt & 1) * 2 + 1]);
        }

        float cmlo = fmaxf(fmaxf(fmaxf(acc[0][0], acc[0][1]), fmaxf(acc[1][0], acc[1][1])),
                           fmaxf(fmaxf(acc[2][0], acc[2][1]), fmaxf(acc[3][0], acc[3][1])));
        float cmhi = fmaxf(fmaxf(fmaxf(acc[0][2], acc[0][3]), fmaxf(acc[1][2], acc[1][3])),
                           fmaxf(fmaxf(acc[2][2], acc[2][3]), fmaxf(acc[3][2], acc[3][3])));
        cmlo = fmaxf(cmlo, __shfl_xor_sync(0xffffffffu, cmlo, 1));
        cmlo = fmaxf(cmlo, __shfl_xor_sync(0xffffffffu, cmlo, 2));
        cmhi = fmaxf(cmhi, __shfl_xor_sync(0xffffffffu, cmhi, 1));
        cmhi = fmaxf(cmhi, __shfl_xor_sync(0xffffffffu, cmhi, 2));
        if (cmlo > mlo) {
            float cs = exp2a(mlo - cmlo);
            Slo *= cs; Wlo0 *= cs; Wlo1 *= cs; Wlo2 *= cs;
            mlo = cmlo;
        }
        if (cmhi > mhi) {
            float cs = exp2a(mhi - cmhi);
            Shi *= cs; Whi0 *= cs; Whi1 *= cs; Whi2 *= cs;
            mhi = cmhi;
        }
#pragma unroll
        for (int nt = 0; nt < 4; ++nt) {
#pragma unroll
            for (int j = 0; j < 2; ++j) {
                const float4 dv = dsm4[nbase + nt * 8 + (lane & 3) * 2 + j];
                float elo = exp2a(acc[nt][j] - mlo);
                float ehi = exp2a(acc[nt][2 + j] - mhi);
                Slo += elo; Shi += ehi;
                Wlo0 = fmaf(elo, dv.x, Wlo0); Wlo1 = fmaf(elo, dv.y, Wlo1); Wlo2 = fmaf(elo, dv.z, Wlo2);
                Whi0 = fmaf(ehi, dv.x, Whi0); Whi1 = fmaf(ehi, dv.y, Whi1); Whi2 = fmaf(ehi, dv.z, Whi2);
            }
        }
    }

#pragma unroll
    for (int d = 1; d <= 2; d <<= 1) {
        Slo += __shfl_xor_sync(0xffffffffu, Slo, d);
        Shi += __shfl_xor_sync(0xffffffffu, Shi, d);
        Wlo0 += __shfl_xor_sync(0xffffffffu, Wlo0, d);
        Wlo1 += __shfl_xor_sync(0xffffffffu, Wlo1, d);
        Wlo2 += __shfl_xor_sync(0xffffffffu, Wlo2, d);
        Whi0 += __shfl_xor_sync(0xffffffffu, Whi0, d);
        Whi1 += __shfl_xor_sync(0xffffffffu, Whi1, d);
        Whi2 += __shfl_xor_sync(0xffffffffu, Whi2, d);
    }
    if ((lane & 3) == 0) {
        const int rlo = g0 + wid * 16 + (lane >> 2);
        const int rhi = rlo + 8;
        const float ilo = 1.0f / Slo, ihi = 1.0f / Shi;
        out[0 * DHW + rlo] = Wlo0 * ilo;
        out[1 * DHW + rlo] = Wlo1 * ilo;
        out[2 * DHW + rlo] = Wlo2 * ilo;
        out[0 * DHW + rhi] = Whi0 * ihi;
        out[1 * DHW + rhi] = Whi1 * ihi;
        out[2 * DHW + rhi] = Whi2 * ihi;
    }
}

// ---------------- launch ----------------
extern "C" void kernel_launch(void* const* d_in, const int* in_sizes, int n_in,
                              void* d_out, int out_size) {
    const float* kpts  = (const float*)d_in[0];
    const float* disp  = (const float*)d_in[1];
    const float* feats = (const float*)d_in[2];
    const float* W0    = (const float*)d_in[3];
    const float* b0    = (const float*)d_in[4];
    float* out = (float*)d_out;

    static int attr_done = 0;
    if (!attr_done) {
        cudaFuncSetAttribute(conv_mma_kernel, cudaFuncAttributeMaxDynamicSharedMemorySize, CONV_SMEM);
        cudaFuncSetAttribute(softmax_mma_kernel, cudaFuncAttributeMaxDynamicSharedMemorySize, SMX_TOTAL);
        attr_done = 1;
    }

    convA_kernel<<<2500, 256>>>(feats);
    convW_kernel<<<5184, 256>>>(W0);
    conv_mma_kernel<<<dim3(48, 24), 256, CONV_SMEM>>>(b0);
    stats_part_kernel<<<512, 256>>>();
    stats_fin_kernel<<<1, 128>>>();
    sample_kernel<<<NK, 128>>>(kpts);
    softmax_mma_kernel<<<DHW / 64, 128, SMX_TOTAL>>>(disp, out);
}

// round 7
// speedup vs baseline: 2.5067x; 1.0312x over previous
#include <cuda_runtime.h>
#include <cuda_bf16.h>
#include <cstdint>

#define DD   48
#define HW   2304
#define DHW  110592
#define NK   512
#define LOG2E 1.4426950408889634f
#define NSTEPS 162

// ---------------- device scratch ----------------
__device__ __nv_bfloat16 d_xv[160002 * 256];          // padded split-bf16 input (+1-pos guard)
__device__ __nv_bfloat16 d_wb[27 * 128 * 384];        // conv weights [tap][co][bhi|bhi|blo]
__device__ __align__(16) __nv_bfloat16 d_fkb[16 * 12288]; // keypoint feats, pre-swizzled
__device__ float d_y[128 * DHW];
__device__ float d_sp[512 * 2];                       // stats partials
__device__ float d_mean[128];
__device__ float d_rstd[128];
__device__ float d_nn[NK];

__device__ __forceinline__ float exp2a(float x) {
    float r; asm("ex2.approx.ftz.f32 %0, %1;" : "=f"(r) : "f"(x)); return r;
}
__device__ __forceinline__ uint32_t smem_u32(const void* p) {
    uint32_t a;
    asm("{ .reg .u64 t; cvta.to.shared.u64 t, %1; cvt.u32.u64 %0, t; }" : "=r"(a) : "l"(p));
    return a;
}
__device__ __forceinline__ void cp16(uint32_t dst, const void* src) {
    asm volatile("cp.async.cg.shared.global [%0], [%1], 16;" :: "r"(dst), "l"(src));
}
__device__ __forceinline__ void cp_commit() { asm volatile("cp.async.commit_group;"); }
__device__ __forceinline__ void ldsm4(uint32_t addr, uint32_t& r0, uint32_t& r1, uint32_t& r2, uint32_t& r3) {
    asm volatile("ldmatrix.sync.aligned.m8n8.x4.shared.b16 {%0,%1,%2,%3}, [%4];"
                 : "=r"(r0), "=r"(r1), "=r"(r2), "=r"(r3) : "r"(addr));
}
__device__ __forceinline__ void mma16816(float* c, const uint32_t* a, uint32_t b0, uint32_t b1) {
    asm volatile("mma.sync.aligned.m16n8k16.row.col.f32.bf16.bf16.f32 "
                 "{%0,%1,%2,%3}, {%4,%5,%6,%7}, {%8,%9}, {%0,%1,%2,%3};"
                 : "+f"(c[0]), "+f"(c[1]), "+f"(c[2]), "+f"(c[3])
                 : "r"(a[0]), "r"(a[1]), "r"(a[2]), "r"(a[3]), "r"(b0), "r"(b1));
}

// ---------------- pack input: padded [z50][y50][x64][hi128|lo128], +1 pos guard ----------------
__global__ void __launch_bounds__(256) convA_kernel(const float* __restrict__ feats) {
    __shared__ __nv_bfloat16 tb[64][264];
    const int r = blockIdx.x;
    const int zs = r / 50, ys = r % 50;
    const int zi = zs - 1, yi = ys - 1;
    const int tid = threadIdx.x;
    const int x = tid & 63, cq = tid >> 6;
    const int xi = x - 1;
    const bool rowok = (zi >= 0 && zi < 48 && yi >= 0 && yi < 48);
    const bool xok = rowok && (xi >= 0 && xi < 48);
#pragma unroll 4
    for (int i = 0; i < 32; ++i) {
        int c = cq * 32 + i;
        float v = 0.f;
        if (xok) {
            if (c < 125)       v = feats[c * DHW + zi * HW + yi * 48 + xi];
            else if (c == 125) v = (2.0f / 47.0f) * (float)xi - 1.0f;
            else if (c == 126) v = (2.0f / 47.0f) * (float)yi - 1.0f;
            else               v = (2.0f / 47.0f) * (float)zi - 1.0f;
        }
        __nv_bfloat16 hi = __float2bfloat16(v);
        tb[x][c] = hi;
        tb[x][128 + c] = __float2bfloat16(v - __bfloat162float(hi));
    }
    __syncthreads();
#pragma unroll
    for (int i = 0; i < 8; ++i) {
        int idx = i * 256 + tid;
        int xr = idx >> 5, k8 = idx & 31;
        float4 val = *(const float4*)&tb[xr][k8 * 8];
        *(float4*)(d_xv + (size_t)(r * 64 + xr + 1) * 256 + k8 * 8) = val;
    }
}

// ---------------- pack conv weights ----------------
__global__ void __launch_bounds__(256) convW_kernel(const float* __restrict__ W0) {
    int idx = blockIdx.x * 256 + threadIdx.x;
    int kk = idx % 384;
    int co = (idx / 384) & 127;
    int tap = idx / (384 * 128);
    int cin = kk & 127;
    float v = W0[co * 3456 + cin * 27 + tap];
    __nv_bfloat16 hi = __float2bfloat16(v);
    d_wb[idx] = (kk < 256) ? hi : __float2bfloat16(v - __bfloat162float(hi));
}

// ---------------- conv3d via mma.sync bf16: 128thr, warp tile 64x64, 2 CTA/SM ----------------
#define STG 32768                 // A 16KB + B 16KB
#define CONV_SMEM (3 * STG)

__global__ void __launch_bounds__(128, 2) conv_mma_kernel(const float* __restrict__ b0g) {
    extern __shared__ char smem[];
    const uint32_t sb = smem_u32(smem);
    const int tid = threadIdx.x;
    const int zc = blockIdx.x;        // 0..47
    const int y0 = blockIdx.y * 2;    // 0..46

    static const int koA_t[6] = {0, 64, 128, 192, 0, 64};

    auto load_stage = [&](int buf, int tap, int s) {
        const int dz = tap / 9;
        const int dyv = (tap % 9) / 3, dx = tap % 3;
        const int koA = koA_t[s];
        const uint32_t ab = sb + buf * STG;
#pragma unroll
        for (int i = 0; i < 8; ++i) {
            const int idx = i * 128 + tid;
            const int row = idx >> 3, u = idx & 7;
            const int y = row >> 6, x = row & 63;
            const size_t pos = (size_t)((zc + dz) * 50 + y0 + y + dyv) * 64 + x + dx;
            cp16(ab + row * 128 + ((u ^ (row & 7)) << 4),
                 d_xv + pos * 256 + koA + u * 8);
        }
        const __nv_bfloat16* bsrc = d_wb + (size_t)tap * 49152 + s * 64;
#pragma unroll
        for (int i = 0; i < 8; ++i) {
            const int idx = i * 128 + tid;
            const int row = idx >> 3, u = idx & 7;
            cp16(ab + 16384 + row * 128 + ((u ^ (row & 7)) << 4),
                 bsrc + (size_t)row * 384 + u * 8);
        }
        cp_commit();
    };

    load_stage(0, 0, 0);
    load_stage(1, 0, 1);

    const int wid = tid >> 5, lane = tid & 31;
    const int wm = wid >> 1, wn = wid & 1;         // 2x2 warps, tile 64x64
    const int rA = wm * 64 + (lane & 15);
    const int uA = lane >> 4;
    const int rB = wn * 64 + ((lane >> 4) << 3) + (lane & 7);
    const int uB = (lane >> 3) & 1;

    float acc[4][8][4];
#pragma unroll
    for (int i = 0; i < 4; ++i)
#pragma unroll
        for (int j = 0; j < 8; ++j)
#pragma unroll
            for (int k = 0; k < 4; ++k) acc[i][j][k] = 0.f;

    for (int step = 0; step < NSTEPS; ++step) {
        if (step < NSTEPS - 1) asm volatile("cp.async.wait_group 1;");
        else                   asm volatile("cp.async.wait_group 0;");
        __syncthreads();
        const int next = step + 2;
        if (next < NSTEPS) load_stage(next % 3, next / 6, next % 6);

        const uint32_t As = sb + (step % 3) * STG;
        const uint32_t Bs = As + 16384;
#pragma unroll
        for (int k16 = 0; k16 < 4; ++k16) {
            uint32_t a[4][4], b4[4][4];
#pragma unroll
            for (int mt = 0; mt < 4; ++mt) {
                const int row = rA + mt * 16;
                ldsm4(As + row * 128 + (((k16 * 2 + uA) ^ (row & 7)) << 4),
                      a[mt][0], a[mt][1], a[mt][2], a[mt][3]);
            }
#pragma unroll
            for (int bt = 0; bt < 4; ++bt) {
                const int row = rB + bt * 16;
                ldsm4(Bs + row * 128 + (((k16 * 2 + uB) ^ (row & 7)) << 4),
                      b4[bt][0], b4[bt][1], b4[bt][2], b4[bt][3]);
            }
#pragma unroll
            for (int mt = 0; mt < 4; ++mt)
#pragma unroll
                for (int nt = 0; nt < 8; ++nt)
                    mma16816(acc[mt][nt], a[mt], b4[nt >> 1][(nt & 1) * 2], b4[nt >> 1][(nt & 1) * 2 + 1]);
        }
    }

#pragma unroll
    for (int mt = 0; mt < 4; ++mt) {
        const int r0 = wm * 64 + mt * 16 + (lane >> 2);
#pragma unroll
        for (int half = 0; half < 2; ++half) {
            const int r = r0 + half * 8;
            const int xxo = r & 63, yy = r >> 6;
            if (xxo < 1 || xxo > 48) continue;
            float* base = d_y + (size_t)zc * HW + (size_t)(y0 + yy) * 48 + (xxo - 1);
#pragma unroll
            for (int nt = 0; nt < 8; ++nt) {
                const int n0 = wn * 64 + nt * 8 + (lane & 3) * 2;
                const float bA = __ldg(&b0g[n0]);
                const float bB = __ldg(&b0g[n0 + 1]);
                base[(size_t)n0 * DHW]       = fmaxf(acc[mt][nt][half * 2 + 0] + bA, 0.f);
                base[(size_t)(n0 + 1) * DHW] = fmaxf(acc[mt][nt][half * 2 + 1] + bB, 0.f);
            }
        }
    }
}

// ---------------- InstanceNorm stats: partials then finalize ----------------
__global__ void __launch_bounds__(256) stats_part_kernel() {
    const int c = blockIdx.x >> 2, part = blockIdx.x & 3;
    const int tid = threadIdx.x;
    const float4* src4 = (const float4*)&d_y[(size_t)c * DHW] + part * 6912;
    float s = 0.f, s2 = 0.f;
    for (int i = tid; i < 6912; i += 256) {
        float4 v = src4[i];
        s  += v.x + v.y + v.z + v.w;
        s2 += v.x * v.x + v.y * v.y + v.z * v.z + v.w * v.w;
    }
#pragma unroll
    for (int o = 16; o > 0; o >>= 1) {
        s  += __shfl_xor_sync(0xffffffffu, s, o);
        s2 += __shfl_xor_sync(0xffffffffu, s2, o);
    }
    __shared__ float rs[8], rs2[8];
    if ((tid & 31) == 0) { rs[tid >> 5] = s; rs2[tid >> 5] = s2; }
    __syncthreads();
    if (tid == 0) {
        float S = 0.f, S2 = 0.f;
#pragma unroll
        for (int i = 0; i < 8; ++i) { S += rs[i]; S2 += rs2[i]; }
        d_sp[blockIdx.x * 2] = S;
        d_sp[blockIdx.x * 2 + 1] = S2;
    }
}
__global__ void __launch_bounds__(128) stats_fin_kernel() {
    const int c = threadIdx.x;
    float S = 0.f, S2 = 0.f;
#pragma unroll
    for (int p = 0; p < 4; ++p) {
        S  += d_sp[(c * 4 + p) * 2];
        S2 += d_sp[(c * 4 + p) * 2 + 1];
    }
    float mean = S * (1.0f / (float)DHW);
    float var  = S2 * (1.0f / (float)DHW) - mean * mean;
    d_mean[c] = mean;
    d_rstd[c] = rsqrtf(var + 1e-5f);
}

// ---------------- keypoint sampling: writes pre-swizzled split-bf16 B + norms ----------------
__global__ void __launch_bounds__(128) sample_kernel(const float* __restrict__ kpts) {
    const int n = blockIdx.x;
    const int c = threadIdx.x;
    __shared__ float pt[3];
    if (c < 3) pt[c] = kpts[n * 3 + c];
    __syncthreads();
    const float ix = (pt[0] + 1.0f) * 0.5f * 47.0f;
    const float iy = (pt[1] + 1.0f) * 0.5f * 47.0f;
    const float iz = (pt[2] + 1.0f) * 0.5f * 47.0f;
    const float x0f = floorf(ix), y0f = floorf(iy), z0f = floorf(iz);
    const float wx = ix - x0f, wy = iy - y0f, wz = iz - z0f;
    int x0 = min(max((int)x0f, 0), 47);
    int y0 = min(max((int)y0f, 0), 47);
    int z0 = min(max((int)z0f, 0), 47);
    int x1 = min(x0 + 1, 47), y1 = min(y0 + 1, 47), z1 = min(z0 + 1, 47);
    const float* vol = &d_y[(size_t)c * DHW];
    float c000 = vol[z0*HW + y0*48 + x0], c001 = vol[z0*HW + y0*48 + x1];
    float c010 = vol[z0*HW + y1*48 + x0], c011 = vol[z0*HW + y1*48 + x1];
    float c100 = vol[z1*HW + y0*48 + x0], c101 = vol[z1*HW + y0*48 + x1];
    float c110 = vol[z1*HW + y1*48 + x0], c111 = vol[z1*HW + y1*48 + x1];
    float v = c000*((1-wz)*(1-wy)*(1-wx)) + c001*((1-wz)*(1-wy)*wx)
            + c010*((1-wz)*wy*(1-wx))     + c011*((1-wz)*wy*wx)
            + c100*(wz*(1-wy)*(1-wx))     + c101*(wz*(1-wy)*wx)
            + c110*(wz*wy*(1-wx))         + c111*(wz*wy*wx);
    float f = (v - d_mean[c]) * d_rstd[c];

    float b = 2.0f * LOG2E * f;
    __nv_bfloat16 bh = __float2bfloat16(b);
    __nv_bfloat16 bl = __float2bfloat16(b - __bfloat162float(bh));
    const int chunk = n >> 5, row = n & 31;
    const int u = (c & 63) >> 3, j = c & 7, ph = c >> 6;
    char* fb = (char*)d_fkb;
    size_t base = (size_t)chunk * 24576 + (size_t)row * 128 + ((u ^ (row & 7)) << 4) + j * 2;
    *(__nv_bfloat16*)(fb + base + (0 + ph) * 4096) = bh;
    *(__nv_bfloat16*)(fb + base + (2 + ph) * 4096) = bh;
    *(__nv_bfloat16*)(fb + base + (4 + ph) * 4096) = bl;

    __shared__ float red[128];
    red[c] = f * f;
    __syncthreads();
    for (int o = 64; o > 0; o >>= 1) {
        if (c < o) red[c] += red[c + o];
        __syncthreads();
    }
    if (c == 0) d_nn[n] = LOG2E * red[0];
}

// ---------------- softmax interpolation via mma.sync ----------------
#define SMX_A    0
#define SMX_B    49152
#define SMX_NN   98304
#define SMX_DSM  100352
#define SMX_MEAN 108544
#define SMX_RSTD 109056
#define SMX_TOTAL 109568

__global__ void __launch_bounds__(128, 2) softmax_mma_kernel(const float* __restrict__ disp,
                                                             float* __restrict__ out) {
    extern __shared__ char sm[];
    const uint32_t sb = smem_u32(sm);
    const int tid = threadIdx.x;
    const int g0 = blockIdx.x * 64;

    float* nns = (float*)(sm + SMX_NN);
    float4* dsm4 = (float4*)(sm + SMX_DSM);
    for (int i = tid; i < NK; i += 128) {
        nns[i] = d_nn[i];
        float4 dv;
        dv.x = disp[i * 3]; dv.y = disp[i * 3 + 1]; dv.z = disp[i * 3 + 2]; dv.w = 0.f;
        dsm4[i] = dv;
    }
    ((float*)(sm + SMX_MEAN))[tid & 127] = d_mean[tid & 127];
    ((float*)(sm + SMX_RSTD))[tid & 127] = d_rstd[tid & 127];

    {
        const char* src = (const char*)d_fkb;
        for (int i = tid; i < 1536; i += 128) cp16(sb + SMX_B + i * 16, src + (size_t)i * 16);
        cp_commit();
    }
    __syncthreads();

    {
        const float* mean = (const float*)(sm + SMX_MEAN);
        const float* rstd = (const float*)(sm + SMX_RSTD);
        const int g = tid & 63, half = tid >> 6;
#pragma unroll
        for (int oct = 0; oct < 8; ++oct) {
            const int c0 = half * 64 + oct * 8;
            union { __nv_bfloat16 h[8]; float4 v; } H, L;
#pragma unroll
            for (int j = 0; j < 8; ++j) {
                float f = d_y[(size_t)(c0 + j) * DHW + g0 + g];
                float a = (f - mean[c0 + j]) * rstd[c0 + j];
                __nv_bfloat16 hh = __float2bfloat16(a);
                H.h[j] = hh;
                L.h[j] = __float2bfloat16(a - __bfloat162float(hh));
            }
            const uint32_t sw = (uint32_t)((oct ^ (g & 7)) << 4);
            char* base = sm + SMX_A + g * 128 + sw;
            *(float4*)(base + (0 + half) * 8192) = H.v;
            *(float4*)(base + (4 + half) * 8192) = H.v;
            *(float4*)(base + (2 + half) * 8192) = L.v;
        }
    }
    __syncthreads();

    const int wid = tid >> 5, lane = tid & 31;
    const int rA = wid * 16 + (lane & 15);
    const int uA = lane >> 4;
    const int rB0 = ((lane >> 4) << 3) + (lane & 7);
    const int uBb = (lane >> 3) & 1;

    float mlo = -1e30f, mhi = -1e30f;
    float Slo = 0.f, Shi = 0.f;
    float Wlo0 = 0.f, Wlo1 = 0.f, Wlo2 = 0.f;
    float Whi0 = 0.f, Whi1 = 0.f, Whi2 = 0.f;

    for (int ci = 0; ci < 16; ++ci) {
        asm volatile("cp.async.wait_group 0;");
        __syncthreads();
        if (ci < 15) {
            const char* src = (const char*)d_fkb + (size_t)(ci + 1) * 24576;
            const uint32_t dst = sb + SMX_B + ((ci + 1) & 1) * 24576;
            for (int i = tid; i < 1536; i += 128) cp16(dst + i * 16, src + (size_t)i * 16);
            cp_commit();
        }
        const uint32_t Bb = sb + SMX_B + (ci & 1) * 24576;
        const int nbase = ci * 32;

        float acc[4][4];
#pragma unroll
        for (int nt = 0; nt < 4; ++nt) {
            float i0 = -nns[nbase + nt * 8 + (lane & 3) * 2];
            float i1 = -nns[nbase + nt * 8 + (lane & 3) * 2 + 1];
            acc[nt][0] = i0; acc[nt][1] = i1; acc[nt][2] = i0; acc[nt][3] = i1;
        }
#pragma unroll
        for (int s = 0; s < 24; ++s) {
            const int pan = s >> 2, inner = s & 3;
            uint32_t a[4];
            ldsm4(sb + SMX_A + pan * 8192 + rA * 128 + (((inner * 2 + uA) ^ (rA & 7)) << 4),
                  a[0], a[1], a[2], a[3]);
            uint32_t b4[2][4];
#pragma unroll
            for (int bt = 0; bt < 2; ++bt) {
                const int row = bt * 16 + rB0;
                ldsm4(Bb + pan * 4096 + row * 128 + (((inner * 2 + uBb) ^ (row & 7)) << 4),
                      b4[bt][0], b4[bt][1], b4[bt][2], b4[bt][3]);
            }
#pragma unroll
            for (int nt = 0; nt < 4; ++nt)
                mma16816(acc[nt], a, b4[nt >> 1][(nt & 1) * 2], b4[nt >> 1][(nt & 1) * 2 + 1]);
        }

        float cmlo = fmaxf(fmaxf(fmaxf(acc[0][0], acc[0][1]), fmaxf(acc[1][0], acc[1][1])),
                           fmaxf(fmaxf(acc[2][0], acc[2][1]), fmaxf(acc[3][0], acc[3][1])));
        float cmhi = fmaxf(fmaxf(fmaxf(acc[0][2], acc[0][3]), fmaxf(acc[1][2], acc[1][3])),
                           fmaxf(fmaxf(acc[2][2], acc[2][3]), fmaxf(acc[3][2], acc[3][3])));
        cmlo = fmaxf(cmlo, __shfl_xor_sync(0xffffffffu, cmlo, 1));
        cmlo = fmaxf(cmlo, __shfl_xor_sync(0xffffffffu, cmlo, 2));
        cmhi = fmaxf(cmhi, __shfl_xor_sync(0xffffffffu, cmhi, 1));
        cmhi = fmaxf(cmhi, __shfl_xor_sync(0xffffffffu, cmhi, 2));
        if (cmlo > mlo) {
            float cs = exp2a(mlo - cmlo);
            Slo *= cs; Wlo0 *= cs; Wlo1 *= cs; Wlo2 *= cs;
            mlo = cmlo;
        }
        if (cmhi > mhi) {
            float cs = exp2a(mhi - cmhi);
            Shi *= cs; Whi0 *= cs; Whi1 *= cs; Whi2 *= cs;
            mhi = cmhi;
        }
#pragma unroll
        for (int nt = 0; nt < 4; ++nt) {
#pragma unroll
            for (int j = 0; j < 2; ++j) {
                const float4 dv = dsm4[nbase + nt * 8 + (lane & 3) * 2 + j];
                float elo = exp2a(acc[nt][j] - mlo);
                float ehi = exp2a(acc[nt][2 + j] - mhi);
                Slo += elo; Shi += ehi;
                Wlo0 = fmaf(elo, dv.x, Wlo0); Wlo1 = fmaf(elo, dv.y, Wlo1); Wlo2 = fmaf(elo, dv.z, Wlo2);
                Whi0 = fmaf(ehi, dv.x, Whi0); Whi1 = fmaf(ehi, dv.y, Whi1); Whi2 = fmaf(ehi, dv.z, Whi2);
            }
        }
    }

#pragma unroll
    for (int d = 1; d <= 2; d <<= 1) {
        Slo += __shfl_xor_sync(0xffffffffu, Slo, d);
        Shi += __shfl_xor_sync(0xffffffffu, Shi, d);
        Wlo0 += __shfl_xor_sync(0xffffffffu, Wlo0, d);
        Wlo1 += __shfl_xor_sync(0xffffffffu, Wlo1, d);
        Wlo2 += __shfl_xor_sync(0xffffffffu, Wlo2, d);
        Whi0 += __shfl_xor_sync(0xffffffffu, Whi0, d);
        Whi1 += __shfl_xor_sync(0xffffffffu, Whi1, d);
        Whi2 += __shfl_xor_sync(0xffffffffu, Whi2, d);
    }
    if ((lane & 3) == 0) {
        const int rlo = g0 + wid * 16 + (lane >> 2);
        const int rhi = rlo + 8;
        const float ilo = 1.0f / Slo, ihi = 1.0f / Shi;
        out[0 * DHW + rlo] = Wlo0 * ilo;
        out[1 * DHW + rlo] = Wlo1 * ilo;
        out[2 * DHW + rlo] = Wlo2 * ilo;
        out[0 * DHW + rhi] = Whi0 * ihi;
        out[1 * DHW + rhi] = Whi1 * ihi;
        out[2 * DHW + rhi] = Whi2 * ihi;
    }
}

// ---------------- launch ----------------
extern "C" void kernel_launch(void* const* d_in, const int* in_sizes, int n_in,
                              void* d_out, int out_size) {
    const float* kpts  = (const float*)d_in[0];
    const float* disp  = (const float*)d_in[1];
    const float* feats = (const float*)d_in[2];
    const float* W0    = (const float*)d_in[3];
    const float* b0    = (const float*)d_in[4];
    float* out = (float*)d_out;

    static int attr_done = 0;
    if (!attr_done) {
        cudaFuncSetAttribute(conv_mma_kernel, cudaFuncAttributeMaxDynamicSharedMemorySize, CONV_SMEM);
        cudaFuncSetAttribute(softmax_mma_kernel, cudaFuncAttributeMaxDynamicSharedMemorySize, SMX_TOTAL);
        attr_done = 1;
    }

    convA_kernel<<<2500, 256>>>(feats);
    convW_kernel<<<5184, 256>>>(W0);
    conv_mma_kernel<<<dim3(48, 24), 128, CONV_SMEM>>>(b0);
    stats_part_kernel<<<512, 256>>>();
    stats_fin_kernel<<<1, 128>>>();
    sample_kernel<<<NK, 128>>>(kpts);
    softmax_mma_kernel<<<DHW / 64, 128, SMX_TOTAL>>>(disp, out);
}

// round 8
// speedup vs baseline: 4.0509x; 1.6160x over previous
#include <cuda_runtime.h>
#include <cuda_bf16.h>
#include <cstdint>

#define DD   48
#define HW   2304
#define DHW  110592
#define NK   512
#define LOG2E 1.4426950408889634f
#define NT   13824            // 24^3 Winograd tiles
#define NMU  64

// ---------------- device scratch ----------------
__device__ float d_xp[50 * 50 * 50 * 128];                          // padded input, voxel-major
__device__ __align__(16) __nv_bfloat16 d_wA[(size_t)NMU * NT * 256]; // transformed input [mu][tile][hi128|lo128]
__device__ __align__(16) __nv_bfloat16 d_wu[NMU * 128 * 384];        // transformed weights [mu][co][bhi|bhi|blo]
__device__ float d_V[(size_t)NMU * NT * 128];                        // GEMM out [mu][tile][co]
__device__ float d_y2[(size_t)DHW * 128];                            // conv out voxel-major [voxel][c]
__device__ __align__(16) __nv_bfloat16 d_fkb[16 * 12288];            // keypoint feats, pre-swizzled
__device__ float d_sp[432 * 256];
__device__ float d_mean[128];
__device__ float d_rstd[128];
__device__ float d_nn[NK];

__device__ __forceinline__ float exp2a(float x) {
    float r; asm("ex2.approx.ftz.f32 %0, %1;" : "=f"(r) : "f"(x)); return r;
}
__device__ __forceinline__ uint32_t smem_u32(const void* p) {
    uint32_t a;
    asm("{ .reg .u64 t; cvta.to.shared.u64 t, %1; cvt.u32.u64 %0, t; }" : "=r"(a) : "l"(p));
    return a;
}
__device__ __forceinline__ void cp16(uint32_t dst, const void* src) {
    asm volatile("cp.async.cg.shared.global [%0], [%1], 16;" :: "r"(dst), "l"(src));
}
__device__ __forceinline__ void cp_commit() { asm volatile("cp.async.commit_group;"); }
__device__ __forceinline__ void ldsm4(uint32_t addr, uint32_t& r0, uint32_t& r1, uint32_t& r2, uint32_t& r3) {
    asm volatile("ldmatrix.sync.aligned.m8n8.x4.shared.b16 {%0,%1,%2,%3}, [%4];"
                 : "=r"(r0), "=r"(r1), "=r"(r2), "=r"(r3) : "r"(addr));
}
__device__ __forceinline__ void mma16816(float* c, const uint32_t* a, uint32_t b0, uint32_t b1) {
    asm volatile("mma.sync.aligned.m16n8k16.row.col.f32.bf16.bf16.f32 "
                 "{%0,%1,%2,%3}, {%4,%5,%6,%7}, {%8,%9}, {%0,%1,%2,%3};"
                 : "+f"(c[0]), "+f"(c[1]), "+f"(c[2]), "+f"(c[3])
                 : "r"(a[0]), "r"(a[1]), "r"(a[2]), "r"(a[3]), "r"(b0), "r"(b1));
}

// ---------------- pad input to [zp50][yp50][xp50][c128] fp32, voxel-major ----------------
__global__ void __launch_bounds__(256) pad_kernel(const float* __restrict__ feats) {
    __shared__ float tb[50][129];
    const int r = blockIdx.x;               // 2500 (zp,yp) rows
    const int zp = r / 50, yp = r % 50;
    const int zi = zp - 1, yi = yp - 1;
    const int tid = threadIdx.x;
    const int x = tid & 63, cq = tid >> 6;
    const int xi = x - 1;
    const bool rowok = (zi >= 0 && zi < 48 && yi >= 0 && yi < 48);
    const bool xok = rowok && (xi >= 0 && xi < 48);
#pragma unroll 4
    for (int i = 0; i < 32; ++i) {
        int c = cq * 32 + i;
        float v = 0.f;
        if (xok) {
            if (c < 125)       v = feats[(size_t)c * DHW + zi * HW + yi * 48 + xi];
            else if (c == 125) v = (2.0f / 47.0f) * (float)xi - 1.0f;
            else if (c == 126) v = (2.0f / 47.0f) * (float)yi - 1.0f;
            else               v = (2.0f / 47.0f) * (float)zi - 1.0f;
        }
        if (x < 50) tb[x][c] = v;
    }
    __syncthreads();
    float* dst = d_xp + (size_t)r * 50 * 128;
    for (int i = tid; i < 1600; i += 256) {
        int xr = i >> 5, c4 = (i & 31) * 4;
        float4 val = make_float4(tb[xr][c4], tb[xr][c4 + 1], tb[xr][c4 + 2], tb[xr][c4 + 3]);
        *(float4*)(dst + xr * 128 + c4) = val;
    }
}

// ---------------- Winograd weight transform: U[mu][co][ci], split-bf16 rows [bhi|bhi|blo] ----------------
__device__ __forceinline__ void grow(int m, float* g) {
    if (m == 0)      { g[0] = 1.f;  g[1] = 0.f;   g[2] = 0.f; }
    else if (m == 1) { g[0] = 0.5f; g[1] = 0.5f;  g[2] = 0.5f; }
    else if (m == 2) { g[0] = 0.5f; g[1] = -0.5f; g[2] = 0.5f; }
    else             { g[0] = 0.f;  g[1] = 0.f;   g[2] = 1.f; }
}
__global__ void __launch_bounds__(128) wino_w_kernel(const float* __restrict__ W0) {
    const int mu = blockIdx.x >> 7, co = blockIdx.x & 127, ci = threadIdx.x;
    const int mz = mu >> 4, my = (mu >> 2) & 3, mx = mu & 3;
    float gz[3], gy[3], gx[3];
    grow(mz, gz); grow(my, gy); grow(mx, gx);
    const float* w = W0 + (size_t)(co * 128 + ci) * 27;
    float u = 0.f;
#pragma unroll
    for (int dz = 0; dz < 3; ++dz)
#pragma unroll
        for (int dy = 0; dy < 3; ++dy)
#pragma unroll
            for (int dx = 0; dx < 3; ++dx)
                u = fmaf(gz[dz] * gy[dy] * gx[dx], __ldg(w + dz * 9 + dy * 3 + dx), u);
    __nv_bfloat16 hi = __float2bfloat16(u);
    __nv_bfloat16 lo = __float2bfloat16(u - __bfloat162float(hi));
    __nv_bfloat16* rrow = d_wu + ((size_t)mu * 128 + co) * 384;
    rrow[ci] = hi; rrow[128 + ci] = hi; rrow[256 + ci] = lo;
}

// ---------------- Winograd input transform: per tile, thread=cin ----------------
__global__ void __launch_bounds__(128) wino_in_kernel() {
    __shared__ __nv_bfloat16 s[NMU * 256];   // [mu][hi128|lo128], 32 KB
    const int t = blockIdx.x;
    const int c = threadIdx.x;
    const int zt = t / 576, yt = (t / 24) % 24, xt = t % 24;
    const float* base = d_xp + ((size_t)((zt * 2) * 50 + yt * 2) * 50 + xt * 2) * 128 + c;

    float d[4][4][4];
#pragma unroll
    for (int z = 0; z < 4; ++z)
#pragma unroll
        for (int y = 0; y < 4; ++y)
#pragma unroll
            for (int x = 0; x < 4; ++x)
                d[z][y][x] = __ldg(base + ((z * 50 + y) * 50 + x) * 128);
    // x-pass
#pragma unroll
    for (int z = 0; z < 4; ++z)
#pragma unroll
        for (int y = 0; y < 4; ++y) {
            float a0 = d[z][y][0], a1 = d[z][y][1], a2 = d[z][y][2], a3 = d[z][y][3];
            d[z][y][0] = a0 - a2; d[z][y][1] = a1 + a2; d[z][y][2] = a2 - a1; d[z][y][3] = a1 - a3;
        }
    // y-pass
#pragma unroll
    for (int z = 0; z < 4; ++z)
#pragma unroll
        for (int x = 0; x < 4; ++x) {
            float a0 = d[z][0][x], a1 = d[z][1][x], a2 = d[z][2][x], a3 = d[z][3][x];
            d[z][0][x] = a0 - a2; d[z][1][x] = a1 + a2; d[z][2][x] = a2 - a1; d[z][3][x] = a1 - a3;
        }
    // z-pass
#pragma unroll
    for (int y = 0; y < 4; ++y)
#pragma unroll
        for (int x = 0; x < 4; ++x) {
            float a0 = d[0][y][x], a1 = d[1][y][x], a2 = d[2][y][x], a3 = d[3][y][x];
            d[0][y][x] = a0 - a2; d[1][y][x] = a1 + a2; d[2][y][x] = a2 - a1; d[3][y][x] = a1 - a3;
        }
    // split to smem
#pragma unroll
    for (int mz = 0; mz < 4; ++mz)
#pragma unroll
        for (int my = 0; my < 4; ++my)
#pragma unroll
            for (int mx = 0; mx < 4; ++mx) {
                int mu = mz * 16 + my * 4 + mx;
                float v = d[mz][my][mx];
                __nv_bfloat16 hi = __float2bfloat16(v);
                s[mu * 256 + c] = hi;
                s[mu * 256 + 128 + c] = __float2bfloat16(v - __bfloat162float(hi));
            }
    __syncthreads();
    const float4* s4 = (const float4*)s;
    float4* dstA = (float4*)d_wA;
#pragma unroll
    for (int i = 0; i < 16; ++i) {
        int idx = i * 128 + c;
        int mu = idx >> 5, ch = idx & 31;
        dstA[((size_t)mu * NT + t) * 32 + ch] = s4[idx];
    }
}

// ---------------- Winograd GEMM: per (mblk, mu), M=128 tiles, N=128, 6 k-steps ----------------
#define STG 32768
#define CONV_SMEM (3 * STG)

__global__ void __launch_bounds__(128, 2) wino_gemm_kernel() {
    extern __shared__ char smem[];
    const uint32_t sb = smem_u32(smem);
    const int tid = threadIdx.x;
    const int tile0 = blockIdx.x * 128;
    const int mu = blockIdx.y;

    static const int koA_t[6] = {0, 64, 128, 192, 0, 64};
    const __nv_bfloat16* Abase = d_wA + ((size_t)mu * NT + tile0) * 256;
    const __nv_bfloat16* Bbase = d_wu + (size_t)mu * 49152;

    auto load_stage = [&](int buf, int s) {
        const int koA = koA_t[s];
        const uint32_t ab = sb + buf * STG;
#pragma unroll
        for (int i = 0; i < 8; ++i) {
            const int idx = i * 128 + tid;
            const int row = idx >> 3, u = idx & 7;
            cp16(ab + row * 128 + ((u ^ (row & 7)) << 4),
                 Abase + (size_t)row * 256 + koA + u * 8);
        }
#pragma unroll
        for (int i = 0; i < 8; ++i) {
            const int idx = i * 128 + tid;
            const int row = idx >> 3, u = idx & 7;
            cp16(ab + 16384 + row * 128 + ((u ^ (row & 7)) << 4),
                 Bbase + (size_t)row * 384 + s * 64 + u * 8);
        }
        cp_commit();
    };

    load_stage(0, 0);
    load_stage(1, 1);

    const int wid = tid >> 5, lane = tid & 31;
    const int wm = wid >> 1, wn = wid & 1;
    const int rA = wm * 64 + (lane & 15);
    const int uA = lane >> 4;
    const int rB = wn * 64 + ((lane >> 4) << 3) + (lane & 7);
    const int uB = (lane >> 3) & 1;

    float acc[4][8][4];
#pragma unroll
    for (int i = 0; i < 4; ++i)
#pragma unroll
        for (int j = 0; j < 8; ++j)
#pragma unroll
            for (int k = 0; k < 4; ++k) acc[i][j][k] = 0.f;

    for (int step = 0; step < 6; ++step) {
        if (step < 5) asm volatile("cp.async.wait_group 1;");
        else          asm volatile("cp.async.wait_group 0;");
        __syncthreads();
        const int next = step + 2;
        if (next < 6) load_stage(next % 3, next);

        const uint32_t As = sb + (step % 3) * STG;
        const uint32_t Bs = As + 16384;
#pragma unroll
        for (int k16 = 0; k16 < 4; ++k16) {
            uint32_t a[4][4], b4[4][4];
#pragma unroll
            for (int mt = 0; mt < 4; ++mt) {
                const int row = rA + mt * 16;
                ldsm4(As + row * 128 + (((k16 * 2 + uA) ^ (row & 7)) << 4),
                      a[mt][0], a[mt][1], a[mt][2], a[mt][3]);
            }
#pragma unroll
            for (int bt = 0; bt < 4; ++bt) {
                const int row = rB + bt * 16;
                ldsm4(Bs + row * 128 + (((k16 * 2 + uB) ^ (row & 7)) << 4),
                      b4[bt][0], b4[bt][1], b4[bt][2], b4[bt][3]);
            }
#pragma unroll
            for (int mt = 0; mt < 4; ++mt)
#pragma unroll
                for (int nt = 0; nt < 8; ++nt)
                    mma16816(acc[mt][nt], a[mt], b4[nt >> 1][(nt & 1) * 2], b4[nt >> 1][(nt & 1) * 2 + 1]);
        }
    }

#pragma unroll
    for (int mt = 0; mt < 4; ++mt) {
        const int r0 = wm * 64 + mt * 16 + (lane >> 2);
#pragma unroll
        for (int half = 0; half < 2; ++half) {
            const int r = r0 + half * 8;
            float* dst = d_V + ((size_t)mu * NT + tile0 + r) * 128;
#pragma unroll
            for (int nt = 0; nt < 8; ++nt) {
                const int n0 = wn * 64 + nt * 8 + (lane & 3) * 2;
                *(float2*)(dst + n0) = make_float2(acc[mt][nt][half * 2 + 0], acc[mt][nt][half * 2 + 1]);
            }
        }
    }
}

// ---------------- Winograd output transform + bias + relu -> d_y2 voxel-major ----------------
__global__ void __launch_bounds__(128) wino_out_kernel(const float* __restrict__ b0) {
    const int t = blockIdx.x;
    const int c = threadIdx.x;
    const int zt = t / 576, yt = (t / 24) % 24, xt = t % 24;
    const float* src = d_V + (size_t)t * 128 + c;
    float v[4][4][4];
#pragma unroll
    for (int mz = 0; mz < 4; ++mz)
#pragma unroll
        for (int my = 0; my < 4; ++my)
#pragma unroll
            for (int mx = 0; mx < 4; ++mx)
                v[mz][my][mx] = __ldg(src + (size_t)(mz * 16 + my * 4 + mx) * NT * 128);
    // x-pass
#pragma unroll
    for (int z = 0; z < 4; ++z)
#pragma unroll
        for (int y = 0; y < 4; ++y) {
            float a0 = v[z][y][0], a1 = v[z][y][1], a2 = v[z][y][2], a3 = v[z][y][3];
            v[z][y][0] = a0 + a1 + a2; v[z][y][1] = a1 - a2 - a3;
        }
    // y-pass
#pragma unroll
    for (int z = 0; z < 4; ++z)
#pragma unroll
        for (int x = 0; x < 2; ++x) {
            float a0 = v[z][0][x], a1 = v[z][1][x], a2 = v[z][2][x], a3 = v[z][3][x];
            v[z][0][x] = a0 + a1 + a2; v[z][1][x] = a1 - a2 - a3;
        }
    // z-pass
    const float bias = __ldg(b0 + c);
#pragma unroll
    for (int y = 0; y < 2; ++y)
#pragma unroll
        for (int x = 0; x < 2; ++x) {
            float a0 = v[0][y][x], a1 = v[1][y][x], a2 = v[2][y][x], a3 = v[3][y][x];
            float o0 = a0 + a1 + a2, o1 = a1 - a2 - a3;
            const int vz0 = (zt * 2) * HW + (yt * 2 + y) * 48 + xt * 2 + x;
            d_y2[(size_t)vz0 * 128 + c] = fmaxf(o0 + bias, 0.f);
            d_y2[(size_t)(vz0 + HW) * 128 + c] = fmaxf(o1 + bias, 0.f);
        }
}

// ---------------- InstanceNorm stats (voxel-major) ----------------
__global__ void __launch_bounds__(128) stats_part_kernel() {
    const int blk = blockIdx.x;       // 432
    const int c = threadIdx.x;
    const float* p = d_y2 + (size_t)blk * 256 * 128 + c;
    float s = 0.f, s2 = 0.f;
#pragma unroll 4
    for (int i = 0; i < 256; ++i) {
        float v = p[(size_t)i * 128];
        s += v; s2 += v * v;
    }
    d_sp[blk * 256 + c] = s;
    d_sp[blk * 256 + 128 + c] = s2;
}
__global__ void __launch_bounds__(128) stats_fin_kernel() {
    const int c = threadIdx.x;
    float S = 0.f, S2 = 0.f;
    for (int b = 0; b < 432; ++b) {
        S  += d_sp[b * 256 + c];
        S2 += d_sp[b * 256 + 128 + c];
    }
    float mean = S * (1.0f / (float)DHW);
    float var  = S2 * (1.0f / (float)DHW) - mean * mean;
    d_mean[c] = mean;
    d_rstd[c] = rsqrtf(var + 1e-5f);
}

// ---------------- keypoint sampling: pre-swizzled split-bf16 B + norms ----------------
__global__ void __launch_bounds__(128) sample_kernel(const float* __restrict__ kpts) {
    const int n = blockIdx.x;
    const int c = threadIdx.x;
    __shared__ float pt[3];
    if (c < 3) pt[c] = kpts[n * 3 + c];
    __syncthreads();
    const float ix = (pt[0] + 1.0f) * 0.5f * 47.0f;
    const float iy = (pt[1] + 1.0f) * 0.5f * 47.0f;
    const float iz = (pt[2] + 1.0f) * 0.5f * 47.0f;
    const float x0f = floorf(ix), y0f = floorf(iy), z0f = floorf(iz);
    const float wx = ix - x0f, wy = iy - y0f, wz = iz - z0f;
    int x0 = min(max((int)x0f, 0), 47);
    int y0 = min(max((int)y0f, 0), 47);
    int z0 = min(max((int)z0f, 0), 47);
    int x1 = min(x0 + 1, 47), y1 = min(y0 + 1, 47), z1 = min(z0 + 1, 47);
    const float* vol = d_y2 + c;
    float c000 = vol[(size_t)(z0*HW + y0*48 + x0) * 128], c001 = vol[(size_t)(z0*HW + y0*48 + x1) * 128];
    float c010 = vol[(size_t)(z0*HW + y1*48 + x0) * 128], c011 = vol[(size_t)(z0*HW + y1*48 + x1) * 128];
    float c100 = vol[(size_t)(z1*HW + y0*48 + x0) * 128], c101 = vol[(size_t)(z1*HW + y0*48 + x1) * 128];
    float c110 = vol[(size_t)(z1*HW + y1*48 + x0) * 128], c111 = vol[(size_t)(z1*HW + y1*48 + x1) * 128];
    float v = c000*((1-wz)*(1-wy)*(1-wx)) + c001*((1-wz)*(1-wy)*wx)
            + c010*((1-wz)*wy*(1-wx))     + c011*((1-wz)*wy*wx)
            + c100*(wz*(1-wy)*(1-wx))     + c101*(wz*(1-wy)*wx)
            + c110*(wz*wy*(1-wx))         + c111*(wz*wy*wx);
    float f = (v - d_mean[c]) * d_rstd[c];

    float b = 2.0f * LOG2E * f;
    __nv_bfloat16 bh = __float2bfloat16(b);
    __nv_bfloat16 bl = __float2bfloat16(b - __bfloat162float(bh));
    const int chunk = n >> 5, row = n & 31;
    const int u = (c & 63) >> 3, j = c & 7, ph = c >> 6;
    char* fb = (char*)d_fkb;
    size_t base = (size_t)chunk * 24576 + (size_t)row * 128 + ((u ^ (row & 7)) << 4) + j * 2;
    *(__nv_bfloat16*)(fb + base + (0 + ph) * 4096) = bh;
    *(__nv_bfloat16*)(fb + base + (2 + ph) * 4096) = bh;
    *(__nv_bfloat16*)(fb + base + (4 + ph) * 4096) = bl;

    __shared__ float red[128];
    red[c] = f * f;
    __syncthreads();
    for (int o = 64; o > 0; o >>= 1) {
        if (c < o) red[c] += red[c + o];
        __syncthreads();
    }
    if (c == 0) d_nn[n] = LOG2E * red[0];
}

// ---------------- softmax interpolation via mma.sync ----------------
#define SMX_A    0
#define SMX_B    49152
#define SMX_NN   98304
#define SMX_DSM  100352
#define SMX_MEAN 108544
#define SMX_RSTD 109056
#define SMX_TOTAL 109568

__global__ void __launch_bounds__(128, 2) softmax_mma_kernel(const float* __restrict__ disp,
                                                             float* __restrict__ out) {
    extern __shared__ char sm[];
    const uint32_t sb = smem_u32(sm);
    const int tid = threadIdx.x;
    const int g0 = blockIdx.x * 64;

    float* nns = (float*)(sm + SMX_NN);
    float4* dsm4 = (float4*)(sm + SMX_DSM);
    for (int i = tid; i < NK; i += 128) {
        nns[i] = d_nn[i];
        float4 dv;
        dv.x = disp[i * 3]; dv.y = disp[i * 3 + 1]; dv.z = disp[i * 3 + 2]; dv.w = 0.f;
        dsm4[i] = dv;
    }
    ((float*)(sm + SMX_MEAN))[tid & 127] = d_mean[tid & 127];
    ((float*)(sm + SMX_RSTD))[tid & 127] = d_rstd[tid & 127];

    {
        const char* src = (const char*)d_fkb;
        for (int i = tid; i < 1536; i += 128) cp16(sb + SMX_B + i * 16, src + (size_t)i * 16);
        cp_commit();
    }
    __syncthreads();

    {
        const float* mean = (const float*)(sm + SMX_MEAN);
        const float* rstd = (const float*)(sm + SMX_RSTD);
        const int g = tid & 63, half = tid >> 6;
#pragma unroll
        for (int oct = 0; oct < 8; ++oct) {
            const int c0 = half * 64 + oct * 8;
            const float* srcp = d_y2 + (size_t)(g0 + g) * 128 + c0;
            float4 fa = *(const float4*)srcp;
            float4 fb4 = *(const float4*)(srcp + 4);
            float vv[8] = {fa.x, fa.y, fa.z, fa.w, fb4.x, fb4.y, fb4.z, fb4.w};
            union { __nv_bfloat16 h[8]; float4 v; } H, L;
#pragma unroll
            for (int j = 0; j < 8; ++j) {
                float a = (vv[j] - mean[c0 + j]) * rstd[c0 + j];
                __nv_bfloat16 hh = __float2bfloat16(a);
                H.h[j] = hh;
                L.h[j] = __float2bfloat16(a - __bfloat162float(hh));
            }
            const uint32_t sw = (uint32_t)((oct ^ (g & 7)) << 4);
            char* basep = sm + SMX_A + g * 128 + sw;
            *(float4*)(basep + (0 + half) * 8192) = H.v;
            *(float4*)(basep + (4 + half) * 8192) = H.v;
            *(float4*)(basep + (2 + half) * 8192) = L.v;
        }
    }
    __syncthreads();

    const int wid = tid >> 5, lane = tid & 31;
    const int rA = wid * 16 + (lane & 15);
    const int uA = lane >> 4;
    const int rB0 = ((lane >> 4) << 3) + (lane & 7);
    const int uBb = (lane >> 3) & 1;

    float mlo = -1e30f, mhi = -1e30f;
    float Slo = 0.f, Shi = 0.f;
    float Wlo0 = 0.f, Wlo1 = 0.f, Wlo2 = 0.f;
    float Whi0 = 0.f, Whi1 = 0.f, Whi2 = 0.f;

    for (int ci = 0; ci < 16; ++ci) {
        asm volatile("cp.async.wait_group 0;");
        __syncthreads();
        if (ci < 15) {
            const char* src = (const char*)d_fkb + (size_t)(ci + 1) * 24576;
            const uint32_t dst = sb + SMX_B + ((ci + 1) & 1) * 24576;
            for (int i = tid; i < 1536; i += 128) cp16(dst + i * 16, src + (size_t)i * 16);
            cp_commit();
        }
        const uint32_t Bb = sb + SMX_B + (ci & 1) * 24576;
        const int nbase = ci * 32;

        float acc[4][4];
#pragma unroll
        for (int nt = 0; nt < 4; ++nt) {
            float i0 = -nns[nbase + nt * 8 + (lane & 3) * 2];
            float i1 = -nns[nbase + nt * 8 + (lane & 3) * 2 + 1];
            acc[nt][0] = i0; acc[nt][1] = i1; acc[nt][2] = i0; acc[nt][3] = i1;
        }
#pragma unroll
        for (int s = 0; s < 24; ++s) {
            const int pan = s >> 2, inner = s & 3;
            uint32_t a[4];
            ldsm4(sb + SMX_A + pan * 8192 + rA * 128 + (((inner * 2 + uA) ^ (rA & 7)) << 4),
                  a[0], a[1], a[2], a[3]);
            uint32_t b4[2][4];
#pragma unroll
            for (int bt = 0; bt < 2; ++bt) {
                const int row = bt * 16 + rB0;
                ldsm4(Bb + pan * 4096 + row * 128 + (((inner * 2 + uBb) ^ (row & 7)) << 4),
                      b4[bt][0], b4[bt][1], b4[bt][2], b4[bt][3]);
            }
#pragma unroll
            for (int nt = 0; nt < 4; ++nt)
                mma16816(acc[nt], a, b4[nt >> 1][(nt & 1) * 2], b4[nt >> 1][(nt & 1) * 2 + 1]);
        }

        float cmlo = fmaxf(fmaxf(fmaxf(acc[0][0], acc[0][1]), fmaxf(acc[1][0], acc[1][1])),
                           fmaxf(fmaxf(acc[2][0], acc[2][1]), fmaxf(acc[3][0], acc[3][1])));
        float cmhi = fmaxf(fmaxf(fmaxf(acc[0][2], acc[0][3]), fmaxf(acc[1][2], acc[1][3])),
                           fmaxf(fmaxf(acc[2][2], acc[2][3]), fmaxf(acc[3][2], acc[3][3])));
        cmlo = fmaxf(cmlo, __shfl_xor_sync(0xffffffffu, cmlo, 1));
        cmlo = fmaxf(cmlo, __shfl_xor_sync(0xffffffffu, cmlo, 2));
        cmhi = fmaxf(cmhi, __shfl_xor_sync(0xffffffffu, cmhi, 1));
        cmhi = fmaxf(cmhi, __shfl_xor_sync(0xffffffffu, cmhi, 2));
        if (cmlo > mlo) {
            float cs = exp2a(mlo - cmlo);
            Slo *= cs; Wlo0 *= cs; Wlo1 *= cs; Wlo2 *= cs;
            mlo = cmlo;
        }
        if (cmhi > mhi) {
            float cs = exp2a(mhi - cmhi);
            Shi *= cs; Whi0 *= cs; Whi1 *= cs; Whi2 *= cs;
            mhi = cmhi;
        }
#pragma unroll
        for (int nt = 0; nt < 4; ++nt) {
#pragma unroll
            for (int j = 0; j < 2; ++j) {
                const float4 dv = dsm4[nbase + nt * 8 + (lane & 3) * 2 + j];
                float elo = exp2a(acc[nt][j] - mlo);
                float ehi = exp2a(acc[nt][2 + j] - mhi);
                Slo += elo; Shi += ehi;
                Wlo0 = fmaf(elo, dv.x, Wlo0); Wlo1 = fmaf(elo, dv.y, Wlo1); Wlo2 = fmaf(elo, dv.z, Wlo2);
                Whi0 = fmaf(ehi, dv.x, Whi0); Whi1 = fmaf(ehi, dv.y, Whi1); Whi2 = fmaf(ehi, dv.z, Whi2);
            }
        }
    }

#pragma unroll
    for (int d = 1; d <= 2; d <<= 1) {
        Slo += __shfl_xor_sync(0xffffffffu, Slo, d);
        Shi += __shfl_xor_sync(0xffffffffu, Shi, d);
        Wlo0 += __shfl_xor_sync(0xffffffffu, Wlo0, d);
        Wlo1 += __shfl_xor_sync(0xffffffffu, Wlo1, d);
        Wlo2 += __shfl_xor_sync(0xffffffffu, Wlo2, d);
        Whi0 += __shfl_xor_sync(0xffffffffu, Whi0, d);
        Whi1 += __shfl_xor_sync(0xffffffffu, Whi1, d);
        Whi2 += __shfl_xor_sync(0xffffffffu, Whi2, d);
    }
    if ((lane & 3) == 0) {
        const int rlo = g0 + wid * 16 + (lane >> 2);
        const int rhi = rlo + 8;
        const float ilo = 1.0f / Slo, ihi = 1.0f / Shi;
        out[0 * DHW + rlo] = Wlo0 * ilo;
        out[1 * DHW + rlo] = Wlo1 * ilo;
        out[2 * DHW + rlo] = Wlo2 * ilo;
        out[0 * DHW + rhi] = Whi0 * ihi;
        out[1 * DHW + rhi] = Whi1 * ihi;
        out[2 * DHW + rhi] = Whi2 * ihi;
    }
}

// ---------------- launch ----------------
extern "C" void kernel_launch(void* const* d_in, const int* in_sizes, int n_in,
                              void* d_out, int out_size) {
    const float* kpts  = (const float*)d_in[0];
    const float* disp  = (const float*)d_in[1];
    const float* feats = (const float*)d_in[2];
    const float* W0    = (const float*)d_in[3];
    const float* b0    = (const float*)d_in[4];
    float* out = (float*)d_out;

    static int attr_done = 0;
    if (!attr_done) {
        cudaFuncSetAttribute(wino_gemm_kernel, cudaFuncAttributeMaxDynamicSharedMemorySize, CONV_SMEM);
        cudaFuncSetAttribute(softmax_mma_kernel, cudaFuncAttributeMaxDynamicSharedMemorySize, SMX_TOTAL);
        attr_done = 1;
    }

    pad_kernel<<<2500, 256>>>(feats);
    wino_w_kernel<<<8192, 128>>>(W0);
    wino_in_kernel<<<NT, 128>>>();
    wino_gemm_kernel<<<dim3(108, 64), 128, CONV_SMEM>>>();
    wino_out_kernel<<<NT, 128>>>(b0);
    stats_part_kernel<<<432, 128>>>();
    stats_fin_kernel<<<1, 128>>>();
    sample_kernel<<<NK, 128>>>(kpts);
    softmax_mma_kernel<<<DHW / 64, 128, SMX_TOTAL>>>(disp, out);
}